// round 2
// baseline (speedup 1.0000x reference)
#include <cuda_runtime.h>
#include <float.h>

// ---------------- problem constants ----------------
#define BB   2
#define V_   12000
#define VP   12001          // V + dummy vertex
#define LSP  16
#define M_TOT (BB*VP)       // 24002 rows in all vertex-major GEMMs
#define NCHUNK 94           // ceil(12000/128)

// ---------------- scratch (device globals; no allocations allowed) ----------------
__device__ float g_pfs  [BB*VP*256];
__device__ float g_t256a[BB*VP*256];
__device__ float g_t256b[BB*VP*256];
__device__ float g_f128a[BB*VP*128];
__device__ float g_f128b[BB*VP*128];
__device__ float g_part [BB*NCHUNK*128];
__device__ float g_gfs  [BB*128];
__device__ float g_gterm[BB*256];

// ---------------- flags ----------------
enum { F_RELU = 1, F_ACC = 2, F_ZDUM = 4, F_AVEC = 8 };

// ---------------- packed f32x2 helpers ----------------
#define FMA2(d, a, b) asm("fma.rn.f32x2 %0, %1, %2, %0;" : "+l"(d) : "l"(a), "l"(b))
#define PACKDUP(d, s) asm("mov.b64 %0, {%1, %1};" : "=l"(d) : "f"(s))
#define UNPACK2(lo, hi, s) asm("mov.b64 {%0, %1}, %2;" : "=f"(lo), "=f"(hi) : "l"(s))

// ---------------- generic fused (gather-)GEMM ----------------
// out[m, n] = epi( sum_k A_row(m)[k] * W[k, n] )
//   gather mode: A_row(m)[k] = A[b, idx[v*L + (k>>logC)], k & (C-1)], A = [B, VP, C]
//   plain  mode: A_row(m)[k] = A[(b*Va + min(v,Va-1))*lda + k]
// BM=128, BN=128, BK=16, 256 threads, 8x8 per thread via f32x2, double-buffered.
__global__ __launch_bounds__(256, 2)
void gemm_k(const float* __restrict__ A, const float* __restrict__ W,
            float* __restrict__ out,
            const int* __restrict__ idx,
            const float* __restrict__ bias,       // [N] or null
            const float* __restrict__ bias_b,     // [B, N] or null
            const float* __restrict__ residual,   // same layout as out, or null
            int M, int N, int K, int Va, int lda, int ldw, int ldo,
            int logC, int flags)
{
    const int BM = 128, BN = 128, BK = 16;
    __shared__ float As[2][BK][BM + 4];
    __shared__ float Bs[2][BK][BN];

    const int t   = threadIdx.x;
    const int bm0 = blockIdx.x * BM;
    const int bn0 = blockIdx.y * BN;

    // ---- A-load assignment: rows t>>2 and +64, one float4 of K each (col (t&3)*4)
    const int lrow0 = t >> 2;          // 0..63
    const int lc4   = (t & 3) * 4;     // 0,4,8,12

    const float* abase[2];
    const int*   ibase[2];
#pragma unroll
    for (int r = 0; r < 2; r++) {
        int m = bm0 + lrow0 + r * 64; if (m >= M) m = M - 1;
        int b = m / VP;
        int v = m - b * VP;
        if (idx) {
            abase[r] = A + b * VP * lda;
            ibase[r] = idx + v * LSP;
        } else {
            int va = v; if (va > Va - 1) va = Va - 1;
            abase[r] = A + (b * Va + va) * lda;
            ibase[r] = nullptr;
        }
    }

    // ---- B-load assignment: row t>>4 (0..15), cols (t&15)*8 .. +7 (2 float4)
    const int bkk = t >> 4;
    const int bnn = (t & 15) * 8;

    const int tx = t & 15, ty = t >> 4;
    const int cmask = (1 << logC) - 1;
    const bool avec = (flags & F_AVEC) != 0;

    unsigned long long acc[8][4];
#pragma unroll
    for (int i = 0; i < 8; i++)
#pragma unroll
        for (int j = 0; j < 4; j++) acc[i][j] = 0ull;

    const int nkt = (K + BK - 1) / BK;

    // ---------------- tile loaders ----------------
    float4 av[2];   // A prefetch regs
    float4 bv[2];   // B prefetch regs

    auto load_tile = [&](int kt) {
        int k0 = kt * BK;
#pragma unroll
        for (int r = 0; r < 2; r++) {
            const float* src;
            if (idx) {
                int gi = ibase[r][k0 >> logC];
                src = abase[r] + gi * lda + (k0 & cmask) + lc4;
            } else {
                src = abase[r] + k0 + lc4;
            }
            if (avec) {
                av[r] = *(const float4*)src;
            } else {
                av[r].x = (k0 + lc4 + 0 < K) ? src[0] : 0.f;
                av[r].y = (k0 + lc4 + 1 < K) ? src[1] : 0.f;
                av[r].z = (k0 + lc4 + 2 < K) ? src[2] : 0.f;
                av[r].w = (k0 + lc4 + 3 < K) ? src[3] : 0.f;
            }
        }
        if (k0 + bkk < K) {
            const float* wsrc = W + (k0 + bkk) * ldw + bn0 + bnn;
            bv[0] = *(const float4*)wsrc;
            bv[1] = *(const float4*)(wsrc + 4);
        } else {
            bv[0] = make_float4(0.f, 0.f, 0.f, 0.f);
            bv[1] = bv[0];
        }
    };
    auto store_tile = [&](int p) {
#pragma unroll
        for (int r = 0; r < 2; r++) {
            int row = lrow0 + r * 64;
            As[p][lc4 + 0][row] = av[r].x;
            As[p][lc4 + 1][row] = av[r].y;
            As[p][lc4 + 2][row] = av[r].z;
            As[p][lc4 + 3][row] = av[r].w;
        }
        *(float4*)&Bs[p][bkk][bnn]     = bv[0];
        *(float4*)&Bs[p][bkk][bnn + 4] = bv[1];
    };

    // ---------------- mainloop ----------------
    load_tile(0);
    store_tile(0);
    __syncthreads();

    int p = 0;
    for (int kt = 0; kt < nkt; kt++) {
        if (kt + 1 < nkt) load_tile(kt + 1);

#pragma unroll
        for (int kk = 0; kk < BK; kk++) {
            float4 a0 = *(const float4*)&As[p][kk][ty * 8];
            float4 a1 = *(const float4*)&As[p][kk][ty * 8 + 4];
            const unsigned long long* brow =
                (const unsigned long long*)&Bs[p][kk][tx * 8];
            unsigned long long bp0 = brow[0], bp1 = brow[1],
                               bp2 = brow[2], bp3 = brow[3];
            float a[8] = {a0.x, a0.y, a0.z, a0.w, a1.x, a1.y, a1.z, a1.w};
#pragma unroll
            for (int i = 0; i < 8; i++) {
                unsigned long long ad;
                PACKDUP(ad, a[i]);
                FMA2(acc[i][0], ad, bp0);
                FMA2(acc[i][1], ad, bp1);
                FMA2(acc[i][2], ad, bp2);
                FMA2(acc[i][3], ad, bp3);
            }
        }

        if (kt + 1 < nkt) store_tile(p ^ 1);
        __syncthreads();
        p ^= 1;
    }

    // ---------------- epilogue ----------------
#pragma unroll
    for (int i = 0; i < 8; i++) {
        int m = bm0 + ty * 8 + i;
        if (m >= M) continue;
        int b = m / VP;
        int v = m - b * VP;
        bool zd = (flags & F_ZDUM) && (v == VP - 1);
#pragma unroll
        for (int jp = 0; jp < 4; jp++) {
            float vlo, vhi;
            UNPACK2(vlo, vhi, acc[i][jp]);
            float pair[2] = {vlo, vhi};
#pragma unroll
            for (int h = 0; h < 2; h++) {
                int n = bn0 + tx * 8 + jp * 2 + h;
                if (n >= N) continue;
                float val = pair[h];
                if (bias)     val += bias[n];
                if (bias_b)   val += bias_b[b * N + n];
                if (residual) val += residual[m * ldo + n];
                if (flags & F_ACC) val += out[m * ldo + n];
                if (flags & F_RELU) val = fmaxf(val, 0.f);
                if (zd) val = 0.f;
                out[m * ldo + n] = val;
            }
        }
    }
}

// ---------------- masked global max-pool over v < V_ ----------------
__global__ void maxpool1(const float* __restrict__ f)
{
    int chunk = blockIdx.x, b = blockIdx.y, n = threadIdx.x;  // 128 threads
    int v0 = chunk * 128;
    float m = -FLT_MAX;
    for (int i = 0; i < 128; i++) {
        int v = v0 + i;
        if (v < V_) m = fmaxf(m, f[(b * VP + v) * 128 + n]);
    }
    g_part[(b * NCHUNK + chunk) * 128 + n] = m;
}
__global__ void maxpool2()
{
    int b = blockIdx.x, n = threadIdx.x;
    float m = -FLT_MAX;
    for (int c = 0; c < NCHUNK; c++) m = fmaxf(m, g_part[(b * NCHUNK + c) * 128 + n]);
    g_gfs[b * 128 + n] = m;
}

// ---------------- gterm[b, n] = sum_c gfs[b,c] * Wo1[384+c, n] ----------------
__global__ void gterm_k(const float* __restrict__ Wo1)
{
    int b = blockIdx.x, n = threadIdx.x;   // 256 threads
    float s = 0.f;
    for (int c = 0; c < 128; c++)
        s = fmaf(g_gfs[b * 128 + c], Wo1[(384 + c) * 256 + n], s);
    g_gterm[b * 256 + n] = s;
}

// ---------------- final out = h2 @ Wo3 + bo3, v < V_ only ----------------
__global__ void out_k(const float* __restrict__ h2, const float* __restrict__ Wo3,
                      const float* __restrict__ bo3, float* __restrict__ out)
{
    __shared__ float w[384];
    int t = threadIdx.x;                    // 128 threads = 4 warps
    if (t < 128) { w[t] = Wo3[t]; w[t + 128] = Wo3[t + 128]; w[t + 256] = Wo3[t + 256]; }
    __syncthreads();
    int warp = t >> 5, lane = t & 31;
    int u = blockIdx.x * 4 + warp;          // vertex id in [0, B*V)
    if (u >= BB * V_) return;
    int b = u / V_, v = u - b * V_;
    const float* hrow = h2 + (b * VP + v) * 128;
    float s0 = 0.f, s1 = 0.f, s2 = 0.f;
    for (int c = lane; c < 128; c += 32) {
        float h = hrow[c];
        s0 = fmaf(h, w[c * 3 + 0], s0);
        s1 = fmaf(h, w[c * 3 + 1], s1);
        s2 = fmaf(h, w[c * 3 + 2], s2);
    }
    for (int o = 16; o > 0; o >>= 1) {
        s0 += __shfl_down_sync(0xffffffffu, s0, o);
        s1 += __shfl_down_sync(0xffffffffu, s1, o);
        s2 += __shfl_down_sync(0xffffffffu, s2, o);
    }
    if (lane == 0) {
        out[u * 3 + 0] = s0 + bo3[0];
        out[u * 3 + 1] = s1 + bo3[1];
        out[u * 3 + 2] = s2 + bo3[2];
    }
}

// ---------------- host-side orchestration ----------------
static inline void launch_gemm(const float* A, const float* W, float* o,
                               const int* idx, const float* bias, const float* bias_b,
                               const float* res, int N, int K, int Va, int lda,
                               int ldw, int logC, int flags)
{
    dim3 grid((M_TOT + 127) / 128, (N + 127) / 128);
    gemm_k<<<grid, 256>>>(A, W, o, idx, bias, bias_b, res,
                          M_TOT, N, K, Va, lda, ldw, N, logC, flags);
}

extern "C" void kernel_launch(void* const* d_in, const int* in_sizes, int n_in,
                              void* d_out, int out_size)
{
    (void)in_sizes; (void)n_in; (void)out_size;
    const float* x       = (const float*)d_in[0];
    const int*   sidx    = (const int*)  d_in[1];
    const float* W_point = (const float*)d_in[2];
    const float* res1_W  = (const float*)d_in[3];
    const float* res1_b  = (const float*)d_in[4];
    const float* W_mid   = (const float*)d_in[5];
    const float* ress_W  = (const float*)d_in[6];
    const float* ress_b  = (const float*)d_in[7];
    const float* Wo1     = (const float*)d_in[8];
    const float* bo1     = (const float*)d_in[9];
    const float* Wo2     = (const float*)d_in[10];
    const float* bo2     = (const float*)d_in[11];
    const float* Wo3     = (const float*)d_in[12];
    const float* bo3     = (const float*)d_in[13];
    float* out = (float*)d_out;

    float *pfs, *t256a, *t256b, *f128a, *f128b, *gterm;
    cudaGetSymbolAddress((void**)&pfs,   g_pfs);
    cudaGetSymbolAddress((void**)&t256a, g_t256a);
    cudaGetSymbolAddress((void**)&t256b, g_t256b);
    cudaGetSymbolAddress((void**)&f128a, g_f128a);
    cudaGetSymbolAddress((void**)&f128b, g_f128b);
    cudaGetSymbolAddress((void**)&gterm, g_gterm);

    // 1) pfs = relu(x @ W_point), dummy row zeroed.  K=479 -> guarded scalar A loads.
    launch_gemm(x, W_point, pfs, nullptr, nullptr, nullptr, nullptr,
                256, 479, V_, 479, 256, 0, F_RELU | F_ZDUM);

    // 2) res1 conv1: h = relu(gather(pfs) @ W0 + b0)
    launch_gemm(pfs, res1_W, t256a, sidx, res1_b, nullptr, nullptr,
                256, 16 * 256, VP, 256, 256, 8, F_RELU | F_ZDUM | F_AVEC);
    // 3) res1 conv2 + residual: r1 = relu(gather(h) @ W1 + b1 + pfs)
    launch_gemm(t256a, res1_W + 4096 * 256, t256b, sidx, res1_b + 256, nullptr, pfs,
                256, 16 * 256, VP, 256, 256, 8, F_RELU | F_ZDUM | F_AVEC);

    // 4) fs = (r1 @ W_mid) * zp
    launch_gemm(t256b, W_mid, f128a, nullptr, nullptr, nullptr, nullptr,
                128, 256, VP, 256, 128, 0, F_ZDUM | F_AVEC);

    // 5) gfs = max over v < V
    maxpool1<<<dim3(NCHUNK, BB), 128>>>(f128a);
    maxpool2<<<BB, 128>>>();

    // 6) three residual blocks at C=128
    for (int i = 0; i < 3; i++) {
        const float* W0 = ress_W + (i * 2 + 0) * 2048 * 128;
        const float* W1 = ress_W + (i * 2 + 1) * 2048 * 128;
        const float* b0 = ress_b + (i * 2 + 0) * 128;
        const float* b1 = ress_b + (i * 2 + 1) * 128;
        launch_gemm(f128a, W0, f128b, sidx, b0, nullptr, nullptr,
                    128, 16 * 128, VP, 128, 128, 7, F_RELU | F_ZDUM | F_AVEC);
        launch_gemm(f128b, W1, f128a, sidx, b1, nullptr, f128a,
                    128, 16 * 128, VP, 128, 128, 7, F_RELU | F_ZDUM | F_AVEC);
    }

    // 7) gterm[b] = gfs[b] @ Wo1[384:512]
    gterm_k<<<BB, 256>>>(Wo1);

    // 8) h1 pass 1: pfs @ Wo1[0:256] + bo1 + gterm
    launch_gemm(pfs, Wo1, t256a, nullptr, bo1, gterm, nullptr,
                256, 256, VP, 256, 256, 0, F_AVEC);
    // 9) h1 pass 2 (accumulate + relu): += fs @ Wo1[256:384]
    launch_gemm(f128a, Wo1 + 256 * 256, t256a, nullptr, nullptr, nullptr, nullptr,
                256, 128, VP, 128, 256, 0, F_ACC | F_RELU | F_AVEC);

    // 10) h2 = relu(h1 @ Wo2 + bo2)
    launch_gemm(t256a, Wo2, f128b, nullptr, bo2, nullptr, nullptr,
                128, 256, VP, 256, 128, 0, F_RELU | F_AVEC);

    // 11) out = h2 @ Wo3 + bo3 (non-dummy rows only)
    out_k<<<(BB * V_ + 3) / 4, 128>>>(f128b, Wo3, bo3, out);
}

// round 4
// speedup vs baseline: 2.1206x; 2.1206x over previous
#include <cuda_runtime.h>
#include <cuda_bf16.h>
#include <float.h>
#include <stdint.h>

// ---------------- problem constants ----------------
#define BB   2
#define V_   12000
#define VP   12001
#define LSP  16
#define M_TOT (BB*VP)          // 24002
#define NCHUNK 94

typedef __nv_bfloat16 bf;

// ---------------- scratch (device globals) ----------------
// activations: interleaved bf16 hi/lo in one uint32 word (.x=hi low16, .y=lo high16)
__device__ uint32_t g_Xi [M_TOT*512];   // x padded to 512 ch
__device__ uint32_t g_Hb [M_TOT*384];   // [pfs(256) | fs3(128)]
__device__ uint32_t g_T1 [M_TOT*256];
__device__ uint32_t g_T2 [M_TOT*256];
__device__ uint32_t g_F1 [M_TOT*128];
__device__ uint32_t g_F2 [M_TOT*128];
__device__ uint32_t g_H2 [M_TOT*128];
// weights split to bf16 planes, layout [K][N] (same as input fp32)
__device__ bf g_Wpth[512*256],   g_Wptl[512*256];
__device__ bf g_R1ah[4096*256],  g_R1al[4096*256];
__device__ bf g_R1bh[4096*256],  g_R1bl[4096*256];
__device__ bf g_Wmh [256*128],   g_Wml [256*128];
__device__ bf g_RSh [6*2048*128],g_RSl [6*2048*128];
__device__ bf g_Wo1h[384*256],   g_Wo1l[384*256];
__device__ bf g_Wo2h[256*128],   g_Wo2l[256*128];
// fp32 helpers
__device__ float g_part [BB*NCHUNK*128];
__device__ float g_gfs  [BB*128];
__device__ float g_gterm[BB*256];

enum { F_RELU = 1, F_ZDUM = 2 };

// ---------------- helpers ----------------
__device__ __forceinline__ uint32_t s2u(const void* p) {
    uint32_t a;
    asm("{ .reg .u64 t; cvta.to.shared.u64 t, %1; cvt.u32.u64 %0, t; }" : "=r"(a) : "l"(p));
    return a;
}
__device__ __forceinline__ uint32_t prmt(uint32_t a, uint32_t b, uint32_t s) {
    uint32_t d; asm("prmt.b32 %0,%1,%2,%3;" : "=r"(d) : "r"(a), "r"(b), "r"(s)); return d;
}
__device__ __forceinline__ void ldsm4(uint32_t addr, uint32_t* r) {
    asm volatile("ldmatrix.sync.aligned.m8n8.x4.shared.b16 {%0,%1,%2,%3}, [%4];"
        : "=r"(r[0]), "=r"(r[1]), "=r"(r[2]), "=r"(r[3]) : "r"(addr));
}
__device__ __forceinline__ void ldsm4t(uint32_t addr, uint32_t* r) {
    asm volatile("ldmatrix.sync.aligned.m8n8.x4.trans.shared.b16 {%0,%1,%2,%3}, [%4];"
        : "=r"(r[0]), "=r"(r[1]), "=r"(r[2]), "=r"(r[3]) : "r"(addr));
}
__device__ __forceinline__ void mma_bf16(float* c, const uint32_t* a, const uint32_t* b) {
    asm volatile("mma.sync.aligned.m16n8k16.row.col.f32.bf16.bf16.f32 "
        "{%0,%1,%2,%3}, {%4,%5,%6,%7}, {%8,%9}, {%0,%1,%2,%3};"
        : "+f"(c[0]), "+f"(c[1]), "+f"(c[2]), "+f"(c[3])
        : "r"(a[0]), "r"(a[1]), "r"(a[2]), "r"(a[3]), "r"(b[0]), "r"(b[1]));
}
__device__ __forceinline__ uint32_t packhl(float f) {
    bf h = __float2bfloat16_rn(f);
    bf l = __float2bfloat16_rn(f - __bfloat162float(h));
    return (uint32_t)__bfloat16_as_ushort(h) | ((uint32_t)__bfloat16_as_ushort(l) << 16);
}
__device__ __forceinline__ float unpackhl(uint32_t w) {
    bf h = __ushort_as_bfloat16((unsigned short)(w & 0xffff));
    bf l = __ushort_as_bfloat16((unsigned short)(w >> 16));
    return __bfloat162float(h) + __bfloat162float(l);
}

// ---------------- smem layout (dynamic, bytes) ----------------
// A tile: 2 planes x [128 rows][40 bf16] = 2*10240 ; B tile: 2 planes x [32 k][72 bf16] = 2*4608
#define AS_OFF(p, pl) ((p)*29696u + (pl)*10240u)
#define BS_OFF(p, pl) ((p)*29696u + 20480u + (pl)*4608u)
#define SMEM_DYN 59392

// ---------------- mma.sync bf16x3 fused (gather-)GEMM ----------------
// out[m,n] = epi( sum_k A(m,k) * W(k,n) ), A interleaved hi/lo words, W split planes.
// gather: A(m,k) = Act[b, idx[v*16 + (k>>logC)], k & ((1<<logC)-1)]
__global__ __launch_bounds__(256, 2)
void gemm_tc(const uint32_t* __restrict__ Ag,
             const bf* __restrict__ Wh, const bf* __restrict__ Wl,
             uint32_t* __restrict__ O,
             const int* __restrict__ idx,
             const float* __restrict__ bias, const float* __restrict__ bias_b,
             const uint32_t* __restrict__ Rp,
             int M, int N, int K, int lda, int ldn, int ldo, int ldr,
             int logC, int flags)
{
    extern __shared__ char smem[];
    const uint32_t sbs = s2u(smem);
    const int t = threadIdx.x, wid = t >> 5, lane = t & 31;
    const int bm0 = blockIdx.x * 128, bn0 = blockIdx.y * 64;
    const int wm = (wid >> 1) * 32, wn = (wid & 1) * 32;

    // ---- loader coords
    const int arow = t >> 1, seg = t & 1;              // A: 2 thr/row, 16 ch each
    int mload = bm0 + arow; if (mload >= M) mload = M - 1;
    const int bL = mload / VP, vL = mload - bL * VP;
    const int* ib = idx ? (idx + vL * LSP) : nullptr;
    const long abase0 = idx ? (long)bL * VP * lda : (long)mload * lda;
    const int cmask = (1 << logC) - 1;
    const int brow = t >> 3, bcol = (t & 7) * 8;       // B: [32][64] bf16 per plane

    float acc[2][4][4];
#pragma unroll
    for (int i = 0; i < 2; i++)
#pragma unroll
        for (int j = 0; j < 4; j++)
#pragma unroll
            for (int r = 0; r < 4; r++) acc[i][j][r] = 0.f;

    const int nkt = K >> 5;
    uint4 sa0, sa1, sa2, sa3, sbh, sbl;

    auto gload = [&](int kt) {
        const int k0 = kt << 5;
        long aoff;
        if (idx) aoff = abase0 + (long)ib[k0 >> logC] * lda + (k0 & cmask) + seg * 16;
        else     aoff = abase0 + k0 + seg * 16;
        const uint4* pa = (const uint4*)(Ag + aoff);
        sa0 = pa[0]; sa1 = pa[1]; sa2 = pa[2]; sa3 = pa[3];
        const long woff = (long)(k0 + brow) * ldn + bn0 + bcol;
        sbh = *(const uint4*)(Wh + woff);
        sbl = *(const uint4*)(Wl + woff);
    };
    auto sstore = [&](int p) {
        uint32_t w[16] = { sa0.x, sa0.y, sa0.z, sa0.w, sa1.x, sa1.y, sa1.z, sa1.w,
                           sa2.x, sa2.y, sa2.z, sa2.w, sa3.x, sa3.y, sa3.z, sa3.w };
        uint32_t hi[8], lo[8];
#pragma unroll
        for (int i = 0; i < 8; i++) {
            hi[i] = prmt(w[2 * i], w[2 * i + 1], 0x5410);
            lo[i] = prmt(w[2 * i], w[2 * i + 1], 0x7632);
        }
        const uint32_t ab = (uint32_t)(arow * 80 + seg * 32);
        *(uint4*)(smem + AS_OFF(p, 0) + ab)      = make_uint4(hi[0], hi[1], hi[2], hi[3]);
        *(uint4*)(smem + AS_OFF(p, 0) + ab + 16) = make_uint4(hi[4], hi[5], hi[6], hi[7]);
        *(uint4*)(smem + AS_OFF(p, 1) + ab)      = make_uint4(lo[0], lo[1], lo[2], lo[3]);
        *(uint4*)(smem + AS_OFF(p, 1) + ab + 16) = make_uint4(lo[4], lo[5], lo[6], lo[7]);
        const uint32_t bb = (uint32_t)(brow * 144 + bcol * 2);
        *(uint4*)(smem + BS_OFF(p, 0) + bb) = sbh;
        *(uint4*)(smem + BS_OFF(p, 1) + bb) = sbl;
    };

    const uint32_t la15 = lane & 15, lhi = lane >> 4, l7 = lane & 7, l8 = (lane >> 3) & 1;

    gload(0); sstore(0); __syncthreads();
    int p = 0;
    for (int kt = 0; kt < nkt; kt++) {
        if (kt + 1 < nkt) gload(kt + 1);

#pragma unroll
        for (int ks = 0; ks < 2; ks++) {
            const uint32_t ao = (uint32_t)((wm + la15) * 80 + (ks * 16 + lhi * 8) * 2);
            uint32_t ah0[4], ah1[4], al0[4], al1[4];
            ldsm4(sbs + AS_OFF(p, 0) + ao,        ah0);
            ldsm4(sbs + AS_OFF(p, 0) + ao + 1280, ah1);   // +16 rows * 80B
            ldsm4(sbs + AS_OFF(p, 1) + ao,        al0);
            ldsm4(sbs + AS_OFF(p, 1) + ao + 1280, al1);
            const uint32_t bo = (uint32_t)((ks * 16 + l7 + l8 * 8) * 144 + (wn + lhi * 8) * 2);
            uint32_t bh[8], bl[8];
            ldsm4t(sbs + BS_OFF(p, 0) + bo,      bh);
            ldsm4t(sbs + BS_OFF(p, 0) + bo + 32, bh + 4); // +16 cols * 2B
            ldsm4t(sbs + BS_OFF(p, 1) + bo,      bl);
            ldsm4t(sbs + BS_OFF(p, 1) + bo + 32, bl + 4);
#pragma unroll
            for (int nf = 0; nf < 4; nf++) {
                mma_bf16(acc[0][nf], ah0, bh + nf * 2);
                mma_bf16(acc[0][nf], ah0, bl + nf * 2);
                mma_bf16(acc[0][nf], al0, bh + nf * 2);
                mma_bf16(acc[1][nf], ah1, bh + nf * 2);
                mma_bf16(acc[1][nf], ah1, bl + nf * 2);
                mma_bf16(acc[1][nf], al1, bh + nf * 2);
            }
        }

        if (kt + 1 < nkt) sstore(p ^ 1);
        __syncthreads();
        p ^= 1;
    }

    // ---- epilogue
#pragma unroll
    for (int mf = 0; mf < 2; mf++) {
#pragma unroll
        for (int hh = 0; hh < 2; hh++) {
            const int m = bm0 + wm + mf * 16 + (lane >> 2) + hh * 8;
            if (m >= M) continue;
            const int b = m / VP, v = m - b * VP;
            const bool zd = (flags & F_ZDUM) && (v == V_);
            const long orow = (long)m * ldo;
            const long rrow = (long)m * ldr;
#pragma unroll
            for (int nf = 0; nf < 4; nf++) {
                const int n = bn0 + wn + nf * 8 + 2 * (lane & 3);
                float f0 = acc[mf][nf][hh * 2 + 0];
                float f1 = acc[mf][nf][hh * 2 + 1];
                if (bias)   { f0 += bias[n];           f1 += bias[n + 1]; }
                if (bias_b) { f0 += bias_b[b * N + n]; f1 += bias_b[b * N + n + 1]; }
                if (Rp)     { f0 += unpackhl(Rp[rrow + n]); f1 += unpackhl(Rp[rrow + n + 1]); }
                if (flags & F_RELU) { f0 = fmaxf(f0, 0.f); f1 = fmaxf(f1, 0.f); }
                if (zd) { f0 = 0.f; f1 = 0.f; }
                O[orow + n]     = packhl(f0);
                O[orow + n + 1] = packhl(f1);
            }
        }
    }
}

// ---------------- prep kernels ----------------
__global__ void xprep(const float* __restrict__ x, uint32_t* __restrict__ Xi)
{
    long i = (long)blockIdx.x * 256 + threadIdx.x;
    if (i >= (long)M_TOT * 512) return;
    int m = (int)(i >> 9), k = (int)(i & 511);
    int b = m / VP, v = m - b * VP;
    float val = 0.f;
    if (v < V_ && k < 479) val = x[((long)(b * V_ + v)) * 479 + k];
    Xi[i] = packhl(val);
}
__global__ void wprep(const float* __restrict__ W, bf* __restrict__ oh, bf* __restrict__ ol,
                      int K, int N, int Kpad)
{
    long i = (long)blockIdx.x * 256 + threadIdx.x;
    if (i >= (long)Kpad * N) return;
    int k = (int)(i / N);
    float v = (k < K) ? W[i] : 0.f;
    bf h = __float2bfloat16_rn(v);
    oh[i] = h;
    ol[i] = __float2bfloat16_rn(v - __bfloat162float(h));
}

// ---------------- maxpool / gterm / final ----------------
__global__ void maxpool1(const uint32_t* __restrict__ f)
{
    int chunk = blockIdx.x, b = blockIdx.y, n = threadIdx.x;
    int v0 = chunk * 128;
    float m = -FLT_MAX;
    for (int i = 0; i < 128; i++) {
        int v = v0 + i;
        if (v < V_) m = fmaxf(m, unpackhl(f[(long)(b * VP + v) * 128 + n]));
    }
    g_part[(b * NCHUNK + chunk) * 128 + n] = m;
}
__global__ void maxpool2()
{
    int b = blockIdx.x, n = threadIdx.x;
    float m = -FLT_MAX;
    for (int c = 0; c < NCHUNK; c++) m = fmaxf(m, g_part[(b * NCHUNK + c) * 128 + n]);
    g_gfs[b * 128 + n] = m;
}
__global__ void gterm_k(const float* __restrict__ Wo1)
{
    int b = blockIdx.x, n = threadIdx.x;
    float s = 0.f;
    for (int c = 0; c < 128; c++)
        s = fmaf(g_gfs[b * 128 + c], Wo1[(384 + c) * 256 + n], s);
    g_gterm[b * 256 + n] = s;
}
__global__ void out_k(const uint32_t* __restrict__ h2, const float* __restrict__ Wo3,
                      const float* __restrict__ bo3, float* __restrict__ out)
{
    __shared__ float w[384];
    int t = threadIdx.x;
    if (t < 128) { w[t] = Wo3[t]; w[t + 128] = Wo3[t + 128]; w[t + 256] = Wo3[t + 256]; }
    __syncthreads();
    int warp = t >> 5, lane = t & 31;
    int u = blockIdx.x * 4 + warp;
    if (u >= BB * V_) return;
    int b = u / V_, v = u - b * V_;
    long row = (long)(b * VP + v) * 128;
    float s0 = 0.f, s1 = 0.f, s2 = 0.f;
    for (int c = lane; c < 128; c += 32) {
        float h = unpackhl(h2[row + c]);
        s0 = fmaf(h, w[c * 3 + 0], s0);
        s1 = fmaf(h, w[c * 3 + 1], s1);
        s2 = fmaf(h, w[c * 3 + 2], s2);
    }
    for (int o = 16; o > 0; o >>= 1) {
        s0 += __shfl_down_sync(0xffffffffu, s0, o);
        s1 += __shfl_down_sync(0xffffffffu, s1, o);
        s2 += __shfl_down_sync(0xffffffffu, s2, o);
    }
    if (lane == 0) {
        out[u * 3 + 0] = s0 + bo3[0];
        out[u * 3 + 1] = s1 + bo3[1];
        out[u * 3 + 2] = s2 + bo3[2];
    }
}

// ---------------- host orchestration ----------------
static void* sym(const void* s) { void* p; cudaGetSymbolAddress(&p, s); return p; }

static void G(const uint32_t* A, const bf* Wh, const bf* Wl, uint32_t* O,
              const int* idx, const float* bias, const float* bb, const uint32_t* R,
              int N, int K, int lda, int ldn, int ldo, int ldr, int logC, int flags)
{
    dim3 grid((M_TOT + 127) / 128, N / 64);
    gemm_tc<<<grid, 256, SMEM_DYN>>>(A, Wh, Wl, O, idx, bias, bb, R,
                                     M_TOT, N, K, lda, ldn, ldo, ldr, logC, flags);
}
static void WP(const float* W, bf* oh, bf* ol, int K, int N, int Kpad)
{
    long n = (long)Kpad * N;
    wprep<<<(unsigned)((n + 255) / 256), 256>>>(W, oh, ol, K, N, Kpad);
}

extern "C" void kernel_launch(void* const* d_in, const int* in_sizes, int n_in,
                              void* d_out, int out_size)
{
    (void)in_sizes; (void)n_in; (void)out_size;
    const float* x       = (const float*)d_in[0];
    const int*   sidx    = (const int*)  d_in[1];
    const float* W_point = (const float*)d_in[2];
    const float* res1_W  = (const float*)d_in[3];
    const float* res1_b  = (const float*)d_in[4];
    const float* W_mid   = (const float*)d_in[5];
    const float* ress_W  = (const float*)d_in[6];
    const float* ress_b  = (const float*)d_in[7];
    const float* Wo1     = (const float*)d_in[8];
    const float* bo1     = (const float*)d_in[9];
    const float* Wo2     = (const float*)d_in[10];
    const float* bo2     = (const float*)d_in[11];
    const float* Wo3     = (const float*)d_in[12];
    const float* bo3     = (const float*)d_in[13];
    float* out = (float*)d_out;

    cudaFuncSetAttribute(gemm_tc, cudaFuncAttributeMaxDynamicSharedMemorySize, SMEM_DYN);

    uint32_t *Xi = (uint32_t*)sym(g_Xi), *Hb = (uint32_t*)sym(g_Hb);
    uint32_t *T1 = (uint32_t*)sym(g_T1), *T2 = (uint32_t*)sym(g_T2);
    uint32_t *F1 = (uint32_t*)sym(g_F1), *F2 = (uint32_t*)sym(g_F2);
    uint32_t *H2 = (uint32_t*)sym(g_H2);
    bf *Wpth = (bf*)sym(g_Wpth), *Wptl = (bf*)sym(g_Wptl);
    bf *R1ah = (bf*)sym(g_R1ah), *R1al = (bf*)sym(g_R1al);
    bf *R1bh = (bf*)sym(g_R1bh), *R1bl = (bf*)sym(g_R1bl);
    bf *Wmh  = (bf*)sym(g_Wmh),  *Wml  = (bf*)sym(g_Wml);
    bf *RSh  = (bf*)sym(g_RSh),  *RSl  = (bf*)sym(g_RSl);
    bf *Wo1h = (bf*)sym(g_Wo1h), *Wo1l = (bf*)sym(g_Wo1l);
    bf *Wo2h = (bf*)sym(g_Wo2h), *Wo2l = (bf*)sym(g_Wo2l);
    float* gterm = (float*)sym(g_gterm);

    // ---- prep
    xprep<<<(unsigned)(((long)M_TOT * 512 + 255) / 256), 256>>>(x, Xi);
    WP(W_point, Wpth, Wptl, 479, 256, 512);
    WP(res1_W,              R1ah, R1al, 4096, 256, 4096);
    WP(res1_W + 4096 * 256, R1bh, R1bl, 4096, 256, 4096);
    WP(W_mid, Wmh, Wml, 256, 128, 256);
    for (int j = 0; j < 6; j++)
        WP(ress_W + (long)j * 2048 * 128, RSh + (long)j * 2048 * 128,
           RSl + (long)j * 2048 * 128, 2048, 128, 2048);
    WP(Wo1, Wo1h, Wo1l, 384, 256, 384);
    WP(Wo2, Wo2h, Wo2l, 256, 128, 256);

    // 1) pfs = relu(x @ W_point) -> Hb cols 0:256
    G(Xi, Wpth, Wptl, Hb, nullptr, nullptr, nullptr, nullptr,
      256, 512, 512, 256, 384, 0, 0, F_RELU | F_ZDUM);
    // 2) res1 conv1: relu(gather(pfs) @ W0 + b0)
    G(Hb, R1ah, R1al, T1, sidx, res1_b, nullptr, nullptr,
      256, 4096, 384, 256, 256, 0, 8, F_RELU | F_ZDUM);
    // 3) res1 conv2 + residual(pfs)
    G(T1, R1bh, R1bl, T2, sidx, res1_b + 256, nullptr, Hb,
      256, 4096, 256, 256, 256, 384, 8, F_RELU | F_ZDUM);
    // 4) fs = (r1 @ W_mid) * zp
    G(T2, Wmh, Wml, F1, nullptr, nullptr, nullptr, nullptr,
      128, 256, 256, 128, 128, 0, 0, F_ZDUM);
    // 5) masked global max-pool
    maxpool1<<<dim3(NCHUNK, BB), 128>>>(F1);
    maxpool2<<<BB, 128>>>();
    // 6) three residual blocks (C=128); block 3 conv2 writes Hb cols 256:384
    for (int i = 0; i < 3; i++) {
        const bf* W0h = RSh + (long)(i * 2 + 0) * 2048 * 128;
        const bf* W0l = RSl + (long)(i * 2 + 0) * 2048 * 128;
        const bf* W1h = RSh + (long)(i * 2 + 1) * 2048 * 128;
        const bf* W1l = RSl + (long)(i * 2 + 1) * 2048 * 128;
        const float* b0 = ress_b + (i * 2 + 0) * 128;
        const float* b1 = ress_b + (i * 2 + 1) * 128;
        G(F1, W0h, W0l, F2, sidx, b0, nullptr, nullptr,
          128, 2048, 128, 128, 128, 0, 7, F_RELU | F_ZDUM);
        if (i < 2)
            G(F2, W1h, W1l, F1, sidx, b1, nullptr, F1,
              128, 2048, 128, 128, 128, 128, 7, F_RELU | F_ZDUM);
        else
            G(F2, W1h, W1l, Hb + 256, sidx, b1, nullptr, F1,
              128, 2048, 128, 128, 384, 128, 7, F_RELU | F_ZDUM);
    }
    // 7) gterm[b] = gfs[b] @ Wo1[384:512]
    gterm_k<<<BB, 256>>>(Wo1);
    // 8) h1 = relu([pfs|fs] @ Wo1[0:384] + bo1 + gterm)
    G(Hb, Wo1h, Wo1l, T1, nullptr, bo1, gterm, nullptr,
      256, 384, 384, 256, 256, 0, 0, F_RELU);
    // 9) h2 = relu(h1 @ Wo2 + bo2)
    G(T1, Wo2h, Wo2l, H2, nullptr, bo2, nullptr, nullptr,
      128, 256, 256, 128, 128, 0, 0, F_RELU);
    // 10) out = h2 @ Wo3 + bo3
    out_k<<<(BB * V_ + 3) / 4, 128>>>(H2, Wo3, bo3, out);
}

// round 5
// speedup vs baseline: 2.7001x; 1.2733x over previous
#include <cuda_runtime.h>
#include <cuda_bf16.h>
#include <float.h>
#include <stdint.h>

// ---------------- problem constants ----------------
#define BB   2
#define V_   12000
#define VP   12001
#define LSP  16
#define M_TOT (BB*VP)          // 24002
#define NCHUNK 94

typedef __nv_bfloat16 bf;

// ---------------- scratch (device globals) ----------------
// activations: two separate bf16 planes (hi, lo)
__device__ bf g_Xh [M_TOT*512], g_Xl [M_TOT*512];
__device__ bf g_Hbh[M_TOT*384], g_Hbl[M_TOT*384];   // [pfs(256) | fs3(128)]
__device__ bf g_T1h[M_TOT*256], g_T1l[M_TOT*256];
__device__ bf g_T2h[M_TOT*256], g_T2l[M_TOT*256];
__device__ bf g_F1h[M_TOT*128], g_F1l[M_TOT*128];
__device__ bf g_F2h[M_TOT*128], g_F2l[M_TOT*128];
__device__ bf g_H2h[M_TOT*128], g_H2l[M_TOT*128];
// weights split to bf16 planes, layout [K][N]
__device__ bf g_Wpth[512*256],   g_Wptl[512*256];
__device__ bf g_R1ah[4096*256],  g_R1al[4096*256];
__device__ bf g_R1bh[4096*256],  g_R1bl[4096*256];
__device__ bf g_Wmh [256*128],   g_Wml [256*128];
__device__ bf g_RSh [6*2048*128],g_RSl [6*2048*128];
__device__ bf g_Wo1h[384*256],   g_Wo1l[384*256];
__device__ bf g_Wo2h[256*128],   g_Wo2l[256*128];
// fp32 helpers
__device__ float g_part [BB*NCHUNK*128];
__device__ float g_gfs  [BB*128];
__device__ float g_gterm[BB*256];

enum { F_RELU = 1, F_ZDUM = 2 };

// ---------------- helpers ----------------
__device__ __forceinline__ uint32_t s2u(const void* p) {
    uint32_t a;
    asm("{ .reg .u64 t; cvta.to.shared.u64 t, %1; cvt.u32.u64 %0, t; }" : "=r"(a) : "l"(p));
    return a;
}
__device__ __forceinline__ void ldsm4(uint32_t addr, uint32_t* r) {
    asm volatile("ldmatrix.sync.aligned.m8n8.x4.shared.b16 {%0,%1,%2,%3}, [%4];"
        : "=r"(r[0]), "=r"(r[1]), "=r"(r[2]), "=r"(r[3]) : "r"(addr));
}
__device__ __forceinline__ void ldsm4t(uint32_t addr, uint32_t* r) {
    asm volatile("ldmatrix.sync.aligned.m8n8.x4.trans.shared.b16 {%0,%1,%2,%3}, [%4];"
        : "=r"(r[0]), "=r"(r[1]), "=r"(r[2]), "=r"(r[3]) : "r"(addr));
}
__device__ __forceinline__ void mma_bf16(float* c, const uint32_t* a, const uint32_t* b) {
    asm volatile("mma.sync.aligned.m16n8k16.row.col.f32.bf16.bf16.f32 "
        "{%0,%1,%2,%3}, {%4,%5,%6,%7}, {%8,%9}, {%0,%1,%2,%3};"
        : "+f"(c[0]), "+f"(c[1]), "+f"(c[2]), "+f"(c[3])
        : "r"(a[0]), "r"(a[1]), "r"(a[2]), "r"(a[3]), "r"(b[0]), "r"(b[1]));
}
__device__ __forceinline__ void cpa(uint32_t dst, const void* src) {
    asm volatile("cp.async.ca.shared.global [%0], [%1], 16;" :: "r"(dst), "l"(src) : "memory");
}
#define CPCOMMIT() asm volatile("cp.async.commit_group;" ::: "memory")
#define CPWAIT1()  asm volatile("cp.async.wait_group 1;" ::: "memory")

__device__ __forceinline__ void fsplit2(float f, bf& h, bf& l) {
    h = __float2bfloat16_rn(f);
    l = __float2bfloat16_rn(f - __bfloat162float(h));
}
__device__ __forceinline__ float pjoin(const bf* H, const bf* L, long i) {
    return __bfloat162float(H[i]) + __bfloat162float(L[i]);
}

// ---------------- smem geometry ----------------
#define APITCH 80                        // 64B data + 16B pad (bank stride 20)
#define APL    (128*APITCH)              // 10240 per plane
#define ASZ    (2*APL)                   // 20480

// ---------------- mma.sync bf16x3 fused (gather-)GEMM, cp.async pipelined ----------------
// NB = 64 or 128 (block N tile). 256 threads, 8 warps (4 m x 2 n), warp tile 32 x NB/2.
template<int NB>
__global__ __launch_bounds__(256, 2)
void gemm_tc(const bf* __restrict__ Ah, const bf* __restrict__ Al,
             const bf* __restrict__ Wh, const bf* __restrict__ Wl,
             bf* __restrict__ Oh, bf* __restrict__ Ol,
             const int* __restrict__ idx,
             const float* __restrict__ bias, const float* __restrict__ bias_b,
             const bf* __restrict__ Rh, const bf* __restrict__ Rl,
             int M, int N, int K, int lda, int ldn, int ldo, int ldr,
             int logC, int flags)
{
    constexpr int BP   = NB * 2 + 16;    // B pitch bytes
    constexpr int BPL  = 32 * BP;        // per-plane B stage
    constexpr int BSZ  = 2 * BPL;
    constexpr int STG  = ASZ + BSZ;      // one stage
    constexpr int HALVES = NB / 64;      // 1 or 2
    constexpr int BCH  = 8 * NB;         // B 16B-chunks per stage (both planes)

    extern __shared__ char smem[];
    const uint32_t sbs = s2u(smem);
    const int t = threadIdx.x, wid = t >> 5, lane = t & 31;
    const int bm0 = blockIdx.x * 128, bn0 = blockIdx.y * NB;
    const int wm = (wid >> 1) * 32, wn = (wid & 1) * (NB / 2);

    // ---- A loader setup: thread t handles rows r0, r0+64, col chunk c4 (16B)
    const int r0 = t >> 2, c4 = t & 3;
    const int cmask = (1 << logC) - 1;
    long ab[2]; const int* ib[2];
#pragma unroll
    for (int r = 0; r < 2; r++) {
        int m = bm0 + r0 + r * 64; if (m >= M) m = M - 1;
        int bI = m / VP, v = m - bI * VP;
        if (idx) { ab[r] = (long)bI * VP * lda; ib[r] = idx + v * LSP; }
        else     { ab[r] = (long)m * lda;       ib[r] = nullptr; }
    }

    const uint32_t la15 = lane & 15, lhi = lane >> 4, l7 = lane & 7, l8 = (lane >> 3) & 1;
    const int nkt = K >> 5;

    float acc[2][HALVES * 4][4];
#pragma unroll
    for (int i = 0; i < 2; i++)
#pragma unroll
        for (int j = 0; j < HALVES * 4; j++)
#pragma unroll
            for (int r = 0; r < 4; r++) acc[i][j][r] = 0.f;

    auto issue = [&](int kt, int p) {
        const int k0 = kt << 5;
        const uint32_t base = sbs + p * STG;
        // A (gathered)
#pragma unroll
        for (int r = 0; r < 2; r++) {
            long off = idx ? (ab[r] + (long)ib[r][k0 >> logC] * lda + (k0 & cmask))
                           : (ab[r] + k0);
            const uint32_t da = base + (r0 + r * 64) * APITCH + c4 * 16;
            cpa(da,       Ah + off + c4 * 8);
            cpa(da + APL, Al + off + c4 * 8);
        }
        // B
#pragma unroll
        for (int i = t; i < BCH; i += 256) {
            const int pl  = i / (4 * NB);
            const int rem = i - pl * (4 * NB);
            const int row = rem / (NB / 8);
            const int col = rem - row * (NB / 8);
            const bf* Wp = pl ? Wl : Wh;
            cpa(base + ASZ + pl * BPL + row * BP + col * 16,
                Wp + (long)(k0 + row) * ldn + bn0 + col * 8);
        }
        CPCOMMIT();
    };

    issue(0, 0);
    issue(1, 1);

    int p = 0;
    for (int kt = 0; kt < nkt; kt++) {
        CPWAIT1();
        __syncthreads();
        const uint32_t base = sbs + p * STG;
#pragma unroll
        for (int ks = 0; ks < 2; ks++) {
            const uint32_t ao = base + (wm + la15) * APITCH + (ks * 16 + lhi * 8) * 2;
            uint32_t ah0[4], ah1[4], al0[4], al1[4];
            ldsm4(ao,              ah0);
            ldsm4(ao + 16 * APITCH, ah1);
            ldsm4(ao + APL,              al0);
            ldsm4(ao + APL + 16 * APITCH, al1);
            const uint32_t brow = (uint32_t)(ks * 16 + l7 + l8 * 8) * BP;
#pragma unroll
            for (int h = 0; h < HALVES; h++) {
                const uint32_t bo = base + ASZ + brow + (wn + h * 32 + lhi * 8) * 2;
                uint32_t bh[8], bl[8];
                ldsm4t(bo,            bh);
                ldsm4t(bo + 32,       bh + 4);
                ldsm4t(bo + BPL,      bl);
                ldsm4t(bo + BPL + 32, bl + 4);
#pragma unroll
                for (int nf = 0; nf < 4; nf++) {
                    float* c0 = acc[0][h * 4 + nf];
                    float* c1 = acc[1][h * 4 + nf];
                    mma_bf16(c0, ah0, bh + nf * 2);
                    mma_bf16(c1, ah1, bh + nf * 2);
                    mma_bf16(c0, ah0, bl + nf * 2);
                    mma_bf16(c1, ah1, bl + nf * 2);
                    mma_bf16(c0, al0, bh + nf * 2);
                    mma_bf16(c1, al1, bh + nf * 2);
                }
            }
        }
        __syncthreads();
        if (kt + 2 < nkt) issue(kt + 2, p);
        else CPCOMMIT();
        p ^= 1;
    }

    // ---- epilogue
#pragma unroll
    for (int mf = 0; mf < 2; mf++) {
#pragma unroll
        for (int hh = 0; hh < 2; hh++) {
            const int m = bm0 + wm + mf * 16 + (lane >> 2) + hh * 8;
            if (m >= M) continue;
            const int bI = m / VP, v = m - bI * VP;
            const bool zd = (flags & F_ZDUM) && (v == V_);
            const long orow = (long)m * ldo;
            const long rrow = (long)m * ldr;
#pragma unroll
            for (int h = 0; h < HALVES; h++) {
#pragma unroll
                for (int nf = 0; nf < 4; nf++) {
                    const int n = bn0 + wn + h * 32 + nf * 8 + 2 * (lane & 3);
                    float f0 = acc[mf][h * 4 + nf][hh * 2 + 0];
                    float f1 = acc[mf][h * 4 + nf][hh * 2 + 1];
                    if (bias)   { f0 += bias[n];           f1 += bias[n + 1]; }
                    if (bias_b) { f0 += bias_b[bI * N + n]; f1 += bias_b[bI * N + n + 1]; }
                    if (Rh)     { f0 += pjoin(Rh, Rl, rrow + n); f1 += pjoin(Rh, Rl, rrow + n + 1); }
                    if (flags & F_RELU) { f0 = fmaxf(f0, 0.f); f1 = fmaxf(f1, 0.f); }
                    if (zd) { f0 = 0.f; f1 = 0.f; }
                    bf h0, l0, h1, l1;
                    fsplit2(f0, h0, l0); fsplit2(f1, h1, l1);
                    __nv_bfloat162 ph; ph.x = h0; ph.y = h1;
                    __nv_bfloat162 pl2; pl2.x = l0; pl2.y = l1;
                    *(__nv_bfloat162*)(Oh + orow + n) = ph;
                    *(__nv_bfloat162*)(Ol + orow + n) = pl2;
                }
            }
        }
    }
}

// ---------------- prep kernels ----------------
__global__ void xprep(const float* __restrict__ x, bf* __restrict__ Xh, bf* __restrict__ Xl)
{
    long i = (long)blockIdx.x * 256 + threadIdx.x;
    if (i >= (long)M_TOT * 512) return;
    int m = (int)(i >> 9), k = (int)(i & 511);
    int b = m / VP, v = m - b * VP;
    float val = 0.f;
    if (v < V_ && k < 479) val = x[((long)(b * V_ + v)) * 479 + k];
    fsplit2(val, Xh[i], Xl[i]);
}
__global__ void wprep(const float* __restrict__ W, bf* __restrict__ oh, bf* __restrict__ ol,
                      int K, int N, int Kpad)
{
    long i = (long)blockIdx.x * 256 + threadIdx.x;
    if (i >= (long)Kpad * N) return;
    int k = (int)(i / N);
    float v = (k < K) ? W[i] : 0.f;
    fsplit2(v, oh[i], ol[i]);
}

// ---------------- maxpool / gterm / final ----------------
__global__ void maxpool1(const bf* __restrict__ fh, const bf* __restrict__ fl)
{
    int chunk = blockIdx.x, b = blockIdx.y, n = threadIdx.x;
    int v0 = chunk * 128;
    float m = -FLT_MAX;
    for (int i = 0; i < 128; i++) {
        int v = v0 + i;
        if (v < V_) m = fmaxf(m, pjoin(fh, fl, (long)(b * VP + v) * 128 + n));
    }
    g_part[(b * NCHUNK + chunk) * 128 + n] = m;
}
__global__ void maxpool2()
{
    int b = blockIdx.x, n = threadIdx.x;
    float m = -FLT_MAX;
    for (int c = 0; c < NCHUNK; c++) m = fmaxf(m, g_part[(b * NCHUNK + c) * 128 + n]);
    g_gfs[b * 128 + n] = m;
}
__global__ void gterm_k(const float* __restrict__ Wo1)
{
    int b = blockIdx.x, n = threadIdx.x;
    float s = 0.f;
    for (int c = 0; c < 128; c++)
        s = fmaf(g_gfs[b * 128 + c], Wo1[(384 + c) * 256 + n], s);
    g_gterm[b * 256 + n] = s;
}
__global__ void out_k(const bf* __restrict__ h2h, const bf* __restrict__ h2l,
                      const float* __restrict__ Wo3, const float* __restrict__ bo3,
                      float* __restrict__ out)
{
    __shared__ float w[384];
    int t = threadIdx.x;
    if (t < 128) { w[t] = Wo3[t]; w[t + 128] = Wo3[t + 128]; w[t + 256] = Wo3[t + 256]; }
    __syncthreads();
    int warp = t >> 5, lane = t & 31;
    int u = blockIdx.x * 4 + warp;
    if (u >= BB * V_) return;
    int b = u / V_, v = u - b * V_;
    long row = (long)(b * VP + v) * 128;
    float s0 = 0.f, s1 = 0.f, s2 = 0.f;
    for (int c = lane; c < 128; c += 32) {
        float h = pjoin(h2h, h2l, row + c);
        s0 = fmaf(h, w[c * 3 + 0], s0);
        s1 = fmaf(h, w[c * 3 + 1], s1);
        s2 = fmaf(h, w[c * 3 + 2], s2);
    }
    for (int o = 16; o > 0; o >>= 1) {
        s0 += __shfl_down_sync(0xffffffffu, s0, o);
        s1 += __shfl_down_sync(0xffffffffu, s1, o);
        s2 += __shfl_down_sync(0xffffffffu, s2, o);
    }
    if (lane == 0) {
        out[u * 3 + 0] = s0 + bo3[0];
        out[u * 3 + 1] = s1 + bo3[1];
        out[u * 3 + 2] = s2 + bo3[2];
    }
}

// ---------------- host orchestration ----------------
static void* sym(const void* s) { void* p; cudaGetSymbolAddress(&p, s); return p; }

#define SMEM128 (2*(ASZ + 2*32*(128*2+16)))   // 75776
#define SMEM64  (2*(ASZ + 2*32*(64*2+16)))    // 59392

static void G128(const bf* Ah, const bf* Al, const bf* Wh, const bf* Wl,
                 bf* Oh, bf* Ol, const int* idx, const float* bias, const float* bb,
                 const bf* Rh, const bf* Rl,
                 int N, int K, int lda, int ldn, int ldo, int ldr, int logC, int flags)
{
    dim3 grid((M_TOT + 127) / 128, N / 128);
    gemm_tc<128><<<grid, 256, SMEM128>>>(Ah, Al, Wh, Wl, Oh, Ol, idx, bias, bb, Rh, Rl,
                                         M_TOT, N, K, lda, ldn, ldo, ldr, logC, flags);
}
static void G64(const bf* Ah, const bf* Al, const bf* Wh, const bf* Wl,
                bf* Oh, bf* Ol, const int* idx, const float* bias, const float* bb,
                const bf* Rh, const bf* Rl,
                int N, int K, int lda, int ldn, int ldo, int ldr, int logC, int flags)
{
    dim3 grid((M_TOT + 127) / 128, N / 64);
    gemm_tc<64><<<grid, 256, SMEM64>>>(Ah, Al, Wh, Wl, Oh, Ol, idx, bias, bb, Rh, Rl,
                                       M_TOT, N, K, lda, ldn, ldo, ldr, logC, flags);
}
static void WP(const float* W, bf* oh, bf* ol, int K, int N, int Kpad)
{
    long n = (long)Kpad * N;
    wprep<<<(unsigned)((n + 255) / 256), 256>>>(W, oh, ol, K, N, Kpad);
}

extern "C" void kernel_launch(void* const* d_in, const int* in_sizes, int n_in,
                              void* d_out, int out_size)
{
    (void)in_sizes; (void)n_in; (void)out_size;
    const float* x       = (const float*)d_in[0];
    const int*   sidx    = (const int*)  d_in[1];
    const float* W_point = (const float*)d_in[2];
    const float* res1_W  = (const float*)d_in[3];
    const float* res1_b  = (const float*)d_in[4];
    const float* W_mid   = (const float*)d_in[5];
    const float* ress_W  = (const float*)d_in[6];
    const float* ress_b  = (const float*)d_in[7];
    const float* Wo1     = (const float*)d_in[8];
    const float* bo1     = (const float*)d_in[9];
    const float* Wo2     = (const float*)d_in[10];
    const float* bo2     = (const float*)d_in[11];
    const float* Wo3     = (const float*)d_in[12];
    const float* bo3     = (const float*)d_in[13];
    float* out = (float*)d_out;

    cudaFuncSetAttribute(gemm_tc<128>, cudaFuncAttributeMaxDynamicSharedMemorySize, SMEM128);
    cudaFuncSetAttribute(gemm_tc<64>,  cudaFuncAttributeMaxDynamicSharedMemorySize, SMEM64);

    bf *Xh = (bf*)sym(g_Xh), *Xl = (bf*)sym(g_Xl);
    bf *Hbh = (bf*)sym(g_Hbh), *Hbl = (bf*)sym(g_Hbl);
    bf *T1h = (bf*)sym(g_T1h), *T1l = (bf*)sym(g_T1l);
    bf *T2h = (bf*)sym(g_T2h), *T2l = (bf*)sym(g_T2l);
    bf *F1h = (bf*)sym(g_F1h), *F1l = (bf*)sym(g_F1l);
    bf *F2h = (bf*)sym(g_F2h), *F2l = (bf*)sym(g_F2l);
    bf *H2h = (bf*)sym(g_H2h), *H2l = (bf*)sym(g_H2l);
    bf *Wpth = (bf*)sym(g_Wpth), *Wptl = (bf*)sym(g_Wptl);
    bf *R1ah = (bf*)sym(g_R1ah), *R1al = (bf*)sym(g_R1al);
    bf *R1bh = (bf*)sym(g_R1bh), *R1bl = (bf*)sym(g_R1bl);
    bf *Wmh  = (bf*)sym(g_Wmh),  *Wml  = (bf*)sym(g_Wml);
    bf *RSh  = (bf*)sym(g_RSh),  *RSl  = (bf*)sym(g_RSl);
    bf *Wo1h = (bf*)sym(g_Wo1h), *Wo1l = (bf*)sym(g_Wo1l);
    bf *Wo2h = (bf*)sym(g_Wo2h), *Wo2l = (bf*)sym(g_Wo2l);
    float* gterm = (float*)sym(g_gterm);

    // ---- prep
    xprep<<<(unsigned)(((long)M_TOT * 512 + 255) / 256), 256>>>(x, Xh, Xl);
    WP(W_point, Wpth, Wptl, 479, 256, 512);
    WP(res1_W,              R1ah, R1al, 4096, 256, 4096);
    WP(res1_W + 4096 * 256, R1bh, R1bl, 4096, 256, 4096);
    WP(W_mid, Wmh, Wml, 256, 128, 256);
    for (int j = 0; j < 6; j++)
        WP(ress_W + (long)j * 2048 * 128, RSh + (long)j * 2048 * 128,
           RSl + (long)j * 2048 * 128, 2048, 128, 2048);
    WP(Wo1, Wo1h, Wo1l, 384, 256, 384);
    WP(Wo2, Wo2h, Wo2l, 256, 128, 256);

    // 1) pfs = relu(x @ W_point) -> Hb cols 0:256
    G128(Xh, Xl, Wpth, Wptl, Hbh, Hbl, nullptr, nullptr, nullptr, nullptr, nullptr,
         256, 512, 512, 256, 384, 0, 0, F_RELU | F_ZDUM);
    // 2) res1 conv1: relu(gather(pfs) @ W0 + b0)
    G128(Hbh, Hbl, R1ah, R1al, T1h, T1l, sidx, res1_b, nullptr, nullptr, nullptr,
         256, 4096, 384, 256, 256, 0, 8, F_RELU | F_ZDUM);
    // 3) res1 conv2 + residual(pfs)
    G128(T1h, T1l, R1bh, R1bl, T2h, T2l, sidx, res1_b + 256, nullptr, Hbh, Hbl,
         256, 4096, 256, 256, 256, 384, 8, F_RELU | F_ZDUM);
    // 4) fs = (r1 @ W_mid) * zp
    G128(T2h, T2l, Wmh, Wml, F1h, F1l, nullptr, nullptr, nullptr, nullptr, nullptr,
         128, 256, 256, 128, 128, 0, 0, F_ZDUM);
    // 5) masked global max-pool
    maxpool1<<<dim3(NCHUNK, BB), 128>>>(F1h, F1l);
    maxpool2<<<BB, 128>>>();
    // 6) three residual blocks (C=128); block 3 conv2 writes Hb cols 256:384
    for (int i = 0; i < 3; i++) {
        const bf* W0h = RSh + (long)(i * 2 + 0) * 2048 * 128;
        const bf* W0l = RSl + (long)(i * 2 + 0) * 2048 * 128;
        const bf* W1h = RSh + (long)(i * 2 + 1) * 2048 * 128;
        const bf* W1l = RSl + (long)(i * 2 + 1) * 2048 * 128;
        const float* b0 = ress_b + (i * 2 + 0) * 128;
        const float* b1 = ress_b + (i * 2 + 1) * 128;
        G64(F1h, F1l, W0h, W0l, F2h, F2l, sidx, b0, nullptr, nullptr, nullptr,
            128, 2048, 128, 128, 128, 0, 7, F_RELU | F_ZDUM);
        if (i < 2)
            G64(F2h, F2l, W1h, W1l, F1h, F1l, sidx, b1, nullptr, F1h, F1l,
                128, 2048, 128, 128, 128, 128, 7, F_RELU | F_ZDUM);
        else
            G64(F2h, F2l, W1h, W1l, Hbh + 256, Hbl + 256, sidx, b1, nullptr, F1h, F1l,
                128, 2048, 128, 128, 384, 128, 7, F_RELU | F_ZDUM);
    }
    // 7) gterm[b] = gfs[b] @ Wo1[384:512]
    gterm_k<<<BB, 256>>>(Wo1);
    // 8) h1 = relu([pfs|fs] @ Wo1[0:384] + bo1 + gterm)
    G128(Hbh, Hbl, Wo1h, Wo1l, T1h, T1l, nullptr, bo1, gterm, nullptr, nullptr,
         256, 384, 384, 256, 256, 0, 0, F_RELU);
    // 9) h2 = relu(h1 @ Wo2 + bo2)
    G128(T1h, T1l, Wo2h, Wo2l, H2h, H2l, nullptr, bo2, nullptr, nullptr, nullptr,
         128, 256, 256, 128, 128, 0, 0, F_RELU);
    // 10) out = h2 @ Wo3 + bo3
    out_k<<<(BB * V_ + 3) / 4, 128>>>(H2h, H2l, Wo3, bo3, out);
}

// round 6
// speedup vs baseline: 2.7374x; 1.0138x over previous
#include <cuda_runtime.h>
#include <cuda_bf16.h>
#include <float.h>
#include <stdint.h>

// ---------------- problem constants ----------------
#define BB   2
#define V_   12000
#define VP   12001
#define LSP  16
#define M_TOT (BB*VP)          // 24002
#define NCHUNK 94

typedef __nv_bfloat16 bf;

// ---------------- scratch (device globals) ----------------
__device__ bf g_Xh [M_TOT*512], g_Xl [M_TOT*512];
__device__ bf g_Hbh[M_TOT*384], g_Hbl[M_TOT*384];   // [pfs(256) | fs3(128)]
__device__ bf g_T1h[M_TOT*256], g_T1l[M_TOT*256];
__device__ bf g_T2h[M_TOT*256], g_T2l[M_TOT*256];
__device__ bf g_F1h[M_TOT*128], g_F1l[M_TOT*128];
__device__ bf g_F2h[M_TOT*128], g_F2l[M_TOT*128];
__device__ bf g_H2h[M_TOT*128], g_H2l[M_TOT*128];
__device__ bf g_Wpth[512*256],   g_Wptl[512*256];
__device__ bf g_R1ah[4096*256],  g_R1al[4096*256];
__device__ bf g_R1bh[4096*256],  g_R1bl[4096*256];
__device__ bf g_Wmh [256*128],   g_Wml [256*128];
__device__ bf g_RSh [6*2048*128],g_RSl [6*2048*128];
__device__ bf g_Wo1h[384*256],   g_Wo1l[384*256];
__device__ bf g_Wo2h[256*128],   g_Wo2l[256*128];
__device__ float g_part [BB*NCHUNK*128];
__device__ float g_gfs  [BB*128];
__device__ float g_gterm[BB*256];

enum { F_RELU = 1, F_ZDUM = 2 };

// ---------------- helpers ----------------
__device__ __forceinline__ uint32_t s2u(const void* p) {
    uint32_t a;
    asm("{ .reg .u64 t; cvta.to.shared.u64 t, %1; cvt.u32.u64 %0, t; }" : "=r"(a) : "l"(p));
    return a;
}
__device__ __forceinline__ void ldsm4(uint32_t addr, uint32_t* r) {
    asm volatile("ldmatrix.sync.aligned.m8n8.x4.shared.b16 {%0,%1,%2,%3}, [%4];"
        : "=r"(r[0]), "=r"(r[1]), "=r"(r[2]), "=r"(r[3]) : "r"(addr));
}
__device__ __forceinline__ void ldsm4t(uint32_t addr, uint32_t* r) {
    asm volatile("ldmatrix.sync.aligned.m8n8.x4.trans.shared.b16 {%0,%1,%2,%3}, [%4];"
        : "=r"(r[0]), "=r"(r[1]), "=r"(r[2]), "=r"(r[3]) : "r"(addr));
}
__device__ __forceinline__ void mma_bf16(float* c, const uint32_t* a, const uint32_t* b) {
    asm volatile("mma.sync.aligned.m16n8k16.row.col.f32.bf16.bf16.f32 "
        "{%0,%1,%2,%3}, {%4,%5,%6,%7}, {%8,%9}, {%0,%1,%2,%3};"
        : "+f"(c[0]), "+f"(c[1]), "+f"(c[2]), "+f"(c[3])
        : "r"(a[0]), "r"(a[1]), "r"(a[2]), "r"(a[3]), "r"(b[0]), "r"(b[1]));
}
__device__ __forceinline__ void cpa(uint32_t dst, const void* src) {
    asm volatile("cp.async.ca.shared.global [%0], [%1], 16;" :: "r"(dst), "l"(src) : "memory");
}
#define CPCOMMIT() asm volatile("cp.async.commit_group;" ::: "memory")
#define CPWAIT1()  asm volatile("cp.async.wait_group 1;" ::: "memory")

__device__ __forceinline__ void fsplit2(float f, bf& h, bf& l) {
    h = __float2bfloat16_rn(f);
    l = __float2bfloat16_rn(f - __bfloat162float(h));
}
__device__ __forceinline__ float pjoin(const bf* H, const bf* L, long i) {
    return __bfloat162float(H[i]) + __bfloat162float(L[i]);
}

// ---------------- smem geometry ----------------
#define APITCH 80
#define APL    (128*APITCH)              // 10240 per plane
#define ASZ    (2*APL)                   // 20480

// ---------------- mma.sync bf16x3 fused (gather-)GEMM, 3-stage cp.async ----------------
template<int NB>
__global__ __launch_bounds__(256, 2)
void gemm_tc(const bf* __restrict__ Ah, const bf* __restrict__ Al,
             const bf* __restrict__ Wh, const bf* __restrict__ Wl,
             bf* __restrict__ Oh, bf* __restrict__ Ol,
             const int* __restrict__ idx,
             const float* __restrict__ bias, const float* __restrict__ bias_b,
             const bf* __restrict__ Rh, const bf* __restrict__ Rl,
             int M, int N, int K, int lda, int ldn, int ldo, int ldr,
             int logC, int flags)
{
    constexpr int BP   = NB * 2 + 16;
    constexpr int BPL  = 32 * BP;
    constexpr int BSZ  = 2 * BPL;
    constexpr int STG  = ASZ + BSZ;
    constexpr int HALVES = NB / 64;
    constexpr int BCH  = 8 * NB;

    extern __shared__ char smem[];
    const uint32_t sbs = s2u(smem);
    const int t = threadIdx.x, wid = t >> 5, lane = t & 31;
    const int bm0 = blockIdx.x * 128, bn0 = blockIdx.y * NB;
    const int wm = (wid >> 1) * 32, wn = (wid & 1) * (NB / 2);

    const int r0 = t >> 2, c4 = t & 3;
    const int cmask = (1 << logC) - 1;
    long ab[2]; const int* ib[2];
#pragma unroll
    for (int r = 0; r < 2; r++) {
        int m = bm0 + r0 + r * 64; if (m >= M) m = M - 1;
        int bI = m / VP, v = m - bI * VP;
        if (idx) { ab[r] = (long)bI * VP * lda; ib[r] = idx + v * LSP; }
        else     { ab[r] = (long)m * lda;       ib[r] = nullptr; }
    }

    const uint32_t la15 = lane & 15, lhi = lane >> 4, l7 = lane & 7, l8 = (lane >> 3) & 1;
    const int nkt = K >> 5;

    float acc[2][HALVES * 4][4];
#pragma unroll
    for (int i = 0; i < 2; i++)
#pragma unroll
        for (int j = 0; j < HALVES * 4; j++)
#pragma unroll
            for (int r = 0; r < 4; r++) acc[i][j][r] = 0.f;

    auto issue = [&](int kt, int p) {
        const int k0 = kt << 5;
        const uint32_t base = sbs + p * STG;
#pragma unroll
        for (int r = 0; r < 2; r++) {
            long off = idx ? (ab[r] + (long)ib[r][k0 >> logC] * lda + (k0 & cmask))
                           : (ab[r] + k0);
            const uint32_t da = base + (r0 + r * 64) * APITCH + c4 * 16;
            cpa(da,       Ah + off + c4 * 8);
            cpa(da + APL, Al + off + c4 * 8);
        }
#pragma unroll
        for (int i = t; i < BCH; i += 256) {
            const int pl  = i / (4 * NB);
            const int rem = i - pl * (4 * NB);
            const int row = rem / (NB / 8);
            const int col = rem - row * (NB / 8);
            const bf* Wp = pl ? Wl : Wh;
            cpa(base + ASZ + pl * BPL + row * BP + col * 16,
                Wp + (long)(k0 + row) * ldn + bn0 + col * 8);
        }
        CPCOMMIT();
    };

    issue(0, 0);
    issue(1, 1);

    for (int kt = 0; kt < nkt; kt++) {
        const int p = kt % 3;
        CPWAIT1();
        __syncthreads();
        const uint32_t base = sbs + p * STG;
#pragma unroll
        for (int ks = 0; ks < 2; ks++) {
            const uint32_t ao = base + (wm + la15) * APITCH + (ks * 16 + lhi * 8) * 2;
            uint32_t ah0[4], ah1[4], al0[4], al1[4];
            ldsm4(ao,               ah0);
            ldsm4(ao + 16 * APITCH, ah1);
            ldsm4(ao + APL,               al0);
            ldsm4(ao + APL + 16 * APITCH, al1);
            const uint32_t brow = (uint32_t)(ks * 16 + l7 + l8 * 8) * BP;
#pragma unroll
            for (int h = 0; h < HALVES; h++) {
                const uint32_t bo = base + ASZ + brow + (wn + h * 32 + lhi * 8) * 2;
                uint32_t bh[8], bl[8];
                ldsm4t(bo,            bh);
                ldsm4t(bo + 32,       bh + 4);
                ldsm4t(bo + BPL,      bl);
                ldsm4t(bo + BPL + 32, bl + 4);
                // pass 1: ah * bh  (8 independent MMAs)
#pragma unroll
                for (int nf = 0; nf < 4; nf++) mma_bf16(acc[0][h * 4 + nf], ah0, bh + nf * 2);
#pragma unroll
                for (int nf = 0; nf < 4; nf++) mma_bf16(acc[1][h * 4 + nf], ah1, bh + nf * 2);
                // pass 2: ah * bl
#pragma unroll
                for (int nf = 0; nf < 4; nf++) mma_bf16(acc[0][h * 4 + nf], ah0, bl + nf * 2);
#pragma unroll
                for (int nf = 0; nf < 4; nf++) mma_bf16(acc[1][h * 4 + nf], ah1, bl + nf * 2);
                // pass 3: al * bh
#pragma unroll
                for (int nf = 0; nf < 4; nf++) mma_bf16(acc[0][h * 4 + nf], al0, bh + nf * 2);
#pragma unroll
                for (int nf = 0; nf < 4; nf++) mma_bf16(acc[1][h * 4 + nf], al1, bh + nf * 2);
            }
        }
        if (kt + 2 < nkt) issue(kt + 2, (kt + 2) % 3);
        else CPCOMMIT();
    }

    // ---- epilogue
#pragma unroll
    for (int mf = 0; mf < 2; mf++) {
#pragma unroll
        for (int hh = 0; hh < 2; hh++) {
            const int m = bm0 + wm + mf * 16 + (lane >> 2) + hh * 8;
            if (m >= M) continue;
            const int bI = m / VP, v = m - bI * VP;
            const bool zd = (flags & F_ZDUM) && (v == V_);
            const long orow = (long)m * ldo;
            const long rrow = (long)m * ldr;
#pragma unroll
            for (int h = 0; h < HALVES; h++) {
#pragma unroll
                for (int nf = 0; nf < 4; nf++) {
                    const int n = bn0 + wn + h * 32 + nf * 8 + 2 * (lane & 3);
                    float f0 = acc[mf][h * 4 + nf][hh * 2 + 0];
                    float f1 = acc[mf][h * 4 + nf][hh * 2 + 1];
                    if (bias)   { f0 += bias[n];            f1 += bias[n + 1]; }
                    if (bias_b) { f0 += bias_b[bI * N + n]; f1 += bias_b[bI * N + n + 1]; }
                    if (Rh)     { f0 += pjoin(Rh, Rl, rrow + n); f1 += pjoin(Rh, Rl, rrow + n + 1); }
                    if (flags & F_RELU) { f0 = fmaxf(f0, 0.f); f1 = fmaxf(f1, 0.f); }
                    if (zd) { f0 = 0.f; f1 = 0.f; }
                    bf h0, l0, h1, l1;
                    fsplit2(f0, h0, l0); fsplit2(f1, h1, l1);
                    __nv_bfloat162 ph; ph.x = h0; ph.y = h1;
                    __nv_bfloat162 pl2; pl2.x = l0; pl2.y = l1;
                    *(__nv_bfloat162*)(Oh + orow + n) = ph;
                    *(__nv_bfloat162*)(Ol + orow + n) = pl2;
                }
            }
        }
    }
}

// ---------------- prep kernels ----------------
__global__ void xprep(const float* __restrict__ x, bf* __restrict__ Xh, bf* __restrict__ Xl)
{
    long i = (long)blockIdx.x * 256 + threadIdx.x;
    if (i >= (long)M_TOT * 512) return;
    int m = (int)(i >> 9), k = (int)(i & 511);
    int b = m / VP, v = m - b * VP;
    float val = 0.f;
    if (v < V_ && k < 479) val = x[((long)(b * V_ + v)) * 479 + k];
    fsplit2(val, Xh[i], Xl[i]);
}
__global__ void wprep(const float* __restrict__ W, bf* __restrict__ oh, bf* __restrict__ ol,
                      int K, int N, int Kpad)
{
    long i = (long)blockIdx.x * 256 + threadIdx.x;
    if (i >= (long)Kpad * N) return;
    int k = (int)(i / N);
    float v = (k < K) ? W[i] : 0.f;
    fsplit2(v, oh[i], ol[i]);
}

// ---------------- maxpool / gterm / final ----------------
__global__ void maxpool1(const bf* __restrict__ fh, const bf* __restrict__ fl)
{
    int chunk = blockIdx.x, b = blockIdx.y, n = threadIdx.x;
    int v0 = chunk * 128;
    float m = -FLT_MAX;
    for (int i = 0; i < 128; i++) {
        int v = v0 + i;
        if (v < V_) m = fmaxf(m, pjoin(fh, fl, (long)(b * VP + v) * 128 + n));
    }
    g_part[(b * NCHUNK + chunk) * 128 + n] = m;
}
__global__ void maxpool2()
{
    int b = blockIdx.x, n = threadIdx.x;
    float m = -FLT_MAX;
    for (int c = 0; c < NCHUNK; c++) m = fmaxf(m, g_part[(b * NCHUNK + c) * 128 + n]);
    g_gfs[b * 128 + n] = m;
}
__global__ void gterm_k(const float* __restrict__ Wo1)
{
    int b = blockIdx.x, n = threadIdx.x;
    float s = 0.f;
    for (int c = 0; c < 128; c++)
        s = fmaf(g_gfs[b * 128 + c], Wo1[(384 + c) * 256 + n], s);
    g_gterm[b * 256 + n] = s;
}
__global__ void out_k(const bf* __restrict__ h2h, const bf* __restrict__ h2l,
                      const float* __restrict__ Wo3, const float* __restrict__ bo3,
                      float* __restrict__ out)
{
    __shared__ float w[384];
    int t = threadIdx.x;
    if (t < 128) { w[t] = Wo3[t]; w[t + 128] = Wo3[t + 128]; w[t + 256] = Wo3[t + 256]; }
    __syncthreads();
    int warp = t >> 5, lane = t & 31;
    int u = blockIdx.x * 4 + warp;
    if (u >= BB * V_) return;
    int b = u / V_, v = u - b * V_;
    long row = (long)(b * VP + v) * 128;
    float s0 = 0.f, s1 = 0.f, s2 = 0.f;
    for (int c = lane; c < 128; c += 32) {
        float h = pjoin(h2h, h2l, row + c);
        s0 = fmaf(h, w[c * 3 + 0], s0);
        s1 = fmaf(h, w[c * 3 + 1], s1);
        s2 = fmaf(h, w[c * 3 + 2], s2);
    }
    for (int o = 16; o > 0; o >>= 1) {
        s0 += __shfl_down_sync(0xffffffffu, s0, o);
        s1 += __shfl_down_sync(0xffffffffu, s1, o);
        s2 += __shfl_down_sync(0xffffffffu, s2, o);
    }
    if (lane == 0) {
        out[u * 3 + 0] = s0 + bo3[0];
        out[u * 3 + 1] = s1 + bo3[1];
        out[u * 3 + 2] = s2 + bo3[2];
    }
}

// ---------------- host orchestration ----------------
static void* sym(const void* s) { void* p; cudaGetSymbolAddress(&p, s); return p; }

#define SMEM128 (3*(ASZ + 2*32*(128*2+16)))   // 113664
#define SMEM64  (3*(ASZ + 2*32*(64*2+16)))    // 89088

static void G128(const bf* Ah, const bf* Al, const bf* Wh, const bf* Wl,
                 bf* Oh, bf* Ol, const int* idx, const float* bias, const float* bb,
                 const bf* Rh, const bf* Rl,
                 int N, int K, int lda, int ldn, int ldo, int ldr, int logC, int flags)
{
    dim3 grid((M_TOT + 127) / 128, N / 128);
    gemm_tc<128><<<grid, 256, SMEM128>>>(Ah, Al, Wh, Wl, Oh, Ol, idx, bias, bb, Rh, Rl,
                                         M_TOT, N, K, lda, ldn, ldo, ldr, logC, flags);
}
static void G64(const bf* Ah, const bf* Al, const bf* Wh, const bf* Wl,
                bf* Oh, bf* Ol, const int* idx, const float* bias, const float* bb,
                const bf* Rh, const bf* Rl,
                int N, int K, int lda, int ldn, int ldo, int ldr, int logC, int flags)
{
    dim3 grid((M_TOT + 127) / 128, N / 64);
    gemm_tc<64><<<grid, 256, SMEM64>>>(Ah, Al, Wh, Wl, Oh, Ol, idx, bias, bb, Rh, Rl,
                                       M_TOT, N, K, lda, ldn, ldo, ldr, logC, flags);
}
static void WP(const float* W, bf* oh, bf* ol, int K, int N, int Kpad)
{
    long n = (long)Kpad * N;
    wprep<<<(unsigned)((n + 255) / 256), 256>>>(W, oh, ol, K, N, Kpad);
}

extern "C" void kernel_launch(void* const* d_in, const int* in_sizes, int n_in,
                              void* d_out, int out_size)
{
    (void)in_sizes; (void)n_in; (void)out_size;
    const float* x       = (const float*)d_in[0];
    const int*   sidx    = (const int*)  d_in[1];
    const float* W_point = (const float*)d_in[2];
    const float* res1_W  = (const float*)d_in[3];
    const float* res1_b  = (const float*)d_in[4];
    const float* W_mid   = (const float*)d_in[5];
    const float* ress_W  = (const float*)d_in[6];
    const float* ress_b  = (const float*)d_in[7];
    const float* Wo1     = (const float*)d_in[8];
    const float* bo1     = (const float*)d_in[9];
    const float* Wo2     = (const float*)d_in[10];
    const float* bo2     = (const float*)d_in[11];
    const float* Wo3     = (const float*)d_in[12];
    const float* bo3     = (const float*)d_in[13];
    float* out = (float*)d_out;

    cudaFuncSetAttribute(gemm_tc<128>, cudaFuncAttributeMaxDynamicSharedMemorySize, SMEM128);
    cudaFuncSetAttribute(gemm_tc<64>,  cudaFuncAttributeMaxDynamicSharedMemorySize, SMEM64);

    bf *Xh = (bf*)sym(g_Xh), *Xl = (bf*)sym(g_Xl);
    bf *Hbh = (bf*)sym(g_Hbh), *Hbl = (bf*)sym(g_Hbl);
    bf *T1h = (bf*)sym(g_T1h), *T1l = (bf*)sym(g_T1l);
    bf *T2h = (bf*)sym(g_T2h), *T2l = (bf*)sym(g_T2l);
    bf *F1h = (bf*)sym(g_F1h), *F1l = (bf*)sym(g_F1l);
    bf *F2h = (bf*)sym(g_F2h), *F2l = (bf*)sym(g_F2l);
    bf *H2h = (bf*)sym(g_H2h), *H2l = (bf*)sym(g_H2l);
    bf *Wpth = (bf*)sym(g_Wpth), *Wptl = (bf*)sym(g_Wptl);
    bf *R1ah = (bf*)sym(g_R1ah), *R1al = (bf*)sym(g_R1al);
    bf *R1bh = (bf*)sym(g_R1bh), *R1bl = (bf*)sym(g_R1bl);
    bf *Wmh  = (bf*)sym(g_Wmh),  *Wml  = (bf*)sym(g_Wml);
    bf *RSh  = (bf*)sym(g_RSh),  *RSl  = (bf*)sym(g_RSl);
    bf *Wo1h = (bf*)sym(g_Wo1h), *Wo1l = (bf*)sym(g_Wo1l);
    bf *Wo2h = (bf*)sym(g_Wo2h), *Wo2l = (bf*)sym(g_Wo2l);
    float* gterm = (float*)sym(g_gterm);

    // ---- prep
    xprep<<<(unsigned)(((long)M_TOT * 512 + 255) / 256), 256>>>(x, Xh, Xl);
    WP(W_point, Wpth, Wptl, 479, 256, 512);
    WP(res1_W,              R1ah, R1al, 4096, 256, 4096);
    WP(res1_W + 4096 * 256, R1bh, R1bl, 4096, 256, 4096);
    WP(W_mid, Wmh, Wml, 256, 128, 256);
    for (int j = 0; j < 6; j++)
        WP(ress_W + (long)j * 2048 * 128, RSh + (long)j * 2048 * 128,
           RSl + (long)j * 2048 * 128, 2048, 128, 2048);
    WP(Wo1, Wo1h, Wo1l, 384, 256, 384);
    WP(Wo2, Wo2h, Wo2l, 256, 128, 256);

    // 1) pfs = relu(x @ W_point) -> Hb cols 0:256
    G128(Xh, Xl, Wpth, Wptl, Hbh, Hbl, nullptr, nullptr, nullptr, nullptr, nullptr,
         256, 512, 512, 256, 384, 0, 0, F_RELU | F_ZDUM);
    // 2) res1 conv1
    G128(Hbh, Hbl, R1ah, R1al, T1h, T1l, sidx, res1_b, nullptr, nullptr, nullptr,
         256, 4096, 384, 256, 256, 0, 8, F_RELU | F_ZDUM);
    // 3) res1 conv2 + residual(pfs)
    G128(T1h, T1l, R1bh, R1bl, T2h, T2l, sidx, res1_b + 256, nullptr, Hbh, Hbl,
         256, 4096, 256, 256, 256, 384, 8, F_RELU | F_ZDUM);
    // 4) fs = (r1 @ W_mid) * zp
    G128(T2h, T2l, Wmh, Wml, F1h, F1l, nullptr, nullptr, nullptr, nullptr, nullptr,
         128, 256, 256, 128, 128, 0, 0, F_ZDUM);
    // 5) masked global max-pool
    maxpool1<<<dim3(NCHUNK, BB), 128>>>(F1h, F1l);
    maxpool2<<<BB, 128>>>();
    // 6) three residual blocks (C=128); block 3 conv2 writes Hb cols 256:384
    for (int i = 0; i < 3; i++) {
        const bf* W0h = RSh + (long)(i * 2 + 0) * 2048 * 128;
        const bf* W0l = RSl + (long)(i * 2 + 0) * 2048 * 128;
        const bf* W1h = RSh + (long)(i * 2 + 1) * 2048 * 128;
        const bf* W1l = RSl + (long)(i * 2 + 1) * 2048 * 128;
        const float* b0 = ress_b + (i * 2 + 0) * 128;
        const float* b1 = ress_b + (i * 2 + 1) * 128;
        G64(F1h, F1l, W0h, W0l, F2h, F2l, sidx, b0, nullptr, nullptr, nullptr,
            128, 2048, 128, 128, 128, 0, 7, F_RELU | F_ZDUM);
        if (i < 2)
            G64(F2h, F2l, W1h, W1l, F1h, F1l, sidx, b1, nullptr, F1h, F1l,
                128, 2048, 128, 128, 128, 128, 7, F_RELU | F_ZDUM);
        else
            G64(F2h, F2l, W1h, W1l, Hbh + 256, Hbl + 256, sidx, b1, nullptr, F1h, F1l,
                128, 2048, 128, 128, 384, 128, 7, F_RELU | F_ZDUM);
    }
    // 7) gterm[b] = gfs[b] @ Wo1[384:512]
    gterm_k<<<BB, 256>>>(Wo1);
    // 8) h1 = relu([pfs|fs] @ Wo1[0:384] + bo1 + gterm)
    G128(Hbh, Hbl, Wo1h, Wo1l, T1h, T1l, nullptr, bo1, gterm, nullptr, nullptr,
         256, 384, 384, 256, 256, 0, 0, F_RELU);
    // 9) h2 = relu(h1 @ Wo2 + bo2)
    G128(T1h, T1l, Wo2h, Wo2l, H2h, H2l, nullptr, bo2, nullptr, nullptr, nullptr,
         128, 256, 256, 128, 128, 0, 0, F_RELU);
    // 10) out = h2 @ Wo3 + bo3
    out_k<<<(BB * V_ + 3) / 4, 128>>>(H2h, H2l, Wo3, bo3, out);
}

// round 7
// speedup vs baseline: 3.8388x; 1.4024x over previous
#include <cuda_runtime.h>
#include <cuda_fp16.h>
#include <float.h>
#include <stdint.h>

// ---------------- problem constants ----------------
#define BB   2
#define V_   12000
#define VP   12001
#define LSP  16
#define M_TOT (BB*VP)          // 24002
#define NCHUNK 94

typedef __half hf;

// ---------------- scratch (device globals) ----------------
// activations: two fp16 planes (hi used by GEMM A; hi+lo for residual/pool/final)
__device__ hf g_Xh [M_TOT*512], g_Xl [M_TOT*512];
__device__ hf g_Hbh[M_TOT*384], g_Hbl[M_TOT*384];   // [pfs(256) | fs3(128)]
__device__ hf g_T1h[M_TOT*256], g_T1l[M_TOT*256];
__device__ hf g_T2h[M_TOT*256], g_T2l[M_TOT*256];
__device__ hf g_F1h[M_TOT*128], g_F1l[M_TOT*128];
__device__ hf g_F2h[M_TOT*128], g_F2l[M_TOT*128];
__device__ hf g_H2h[M_TOT*128], g_H2l[M_TOT*128];
// weights split to fp16 hi/lo planes, layout [K][N]
__device__ hf g_Wpth[512*256],   g_Wptl[512*256];
__device__ hf g_R1ah[4096*256],  g_R1al[4096*256];
__device__ hf g_R1bh[4096*256],  g_R1bl[4096*256];
__device__ hf g_Wmh [256*128],   g_Wml [256*128];
__device__ hf g_RSh [6*2048*128],g_RSl [6*2048*128];
__device__ hf g_Wo1h[384*256],   g_Wo1l[384*256];
__device__ hf g_Wo2h[256*128],   g_Wo2l[256*128];
__device__ float g_part [BB*NCHUNK*128];
__device__ float g_gfs  [BB*128];
__device__ float g_gterm[BB*256];

enum { F_RELU = 1, F_ZDUM = 2 };

// ---------------- helpers ----------------
__device__ __forceinline__ uint32_t s2u(const void* p) {
    uint32_t a;
    asm("{ .reg .u64 t; cvta.to.shared.u64 t, %1; cvt.u32.u64 %0, t; }" : "=r"(a) : "l"(p));
    return a;
}
__device__ __forceinline__ void ldsm4(uint32_t addr, uint32_t* r) {
    asm volatile("ldmatrix.sync.aligned.m8n8.x4.shared.b16 {%0,%1,%2,%3}, [%4];"
        : "=r"(r[0]), "=r"(r[1]), "=r"(r[2]), "=r"(r[3]) : "r"(addr));
}
__device__ __forceinline__ void ldsm4t(uint32_t addr, uint32_t* r) {
    asm volatile("ldmatrix.sync.aligned.m8n8.x4.trans.shared.b16 {%0,%1,%2,%3}, [%4];"
        : "=r"(r[0]), "=r"(r[1]), "=r"(r[2]), "=r"(r[3]) : "r"(addr));
}
__device__ __forceinline__ void mma_f16(float* c, const uint32_t* a, const uint32_t* b) {
    asm volatile("mma.sync.aligned.m16n8k16.row.col.f32.f16.f16.f32 "
        "{%0,%1,%2,%3}, {%4,%5,%6,%7}, {%8,%9}, {%0,%1,%2,%3};"
        : "+f"(c[0]), "+f"(c[1]), "+f"(c[2]), "+f"(c[3])
        : "r"(a[0]), "r"(a[1]), "r"(a[2]), "r"(a[3]), "r"(b[0]), "r"(b[1]));
}
__device__ __forceinline__ void cpa(uint32_t dst, const void* src) {
    asm volatile("cp.async.ca.shared.global [%0], [%1], 16;" :: "r"(dst), "l"(src) : "memory");
}
#define CPCOMMIT() asm volatile("cp.async.commit_group;" ::: "memory")
#define CPWAIT1()  asm volatile("cp.async.wait_group 1;" ::: "memory")

__device__ __forceinline__ void fsplit2(float f, hf& h, hf& l) {
    h = __float2half_rn(f);
    l = __float2half_rn(f - __half2float(h));
}
__device__ __forceinline__ float pjoin(const hf* H, const hf* L, long i) {
    return __half2float(H[i]) + __half2float(L[i]);
}

// ---------------- smem geometry ----------------
#define APITCH 80
#define ASTG   (128*APITCH)              // 10240 (single A plane)

// ---------------- mma.sync fp16x2 fused (gather-)GEMM, 3-stage cp.async ----------------
template<int NB>
__global__ __launch_bounds__(256, 2)
void gemm_tc(const hf* __restrict__ Ah,
             const hf* __restrict__ Wh, const hf* __restrict__ Wl,
             hf* __restrict__ Oh, hf* __restrict__ Ol,
             const int* __restrict__ idx,
             const float* __restrict__ bias, const float* __restrict__ bias_b,
             const hf* __restrict__ Rh, const hf* __restrict__ Rl,
             int M, int N, int K, int lda, int ldn, int ldo, int ldr,
             int logC, int flags)
{
    constexpr int BP   = NB * 2 + 16;
    constexpr int BPL  = 32 * BP;
    constexpr int STG  = ASTG + 2 * BPL;
    constexpr int HALVES = NB / 64;
    constexpr int BCH  = 8 * NB;

    extern __shared__ char smem[];
    const uint32_t sbs = s2u(smem);
    const int t = threadIdx.x, wid = t >> 5, lane = t & 31;
    const int bm0 = blockIdx.x * 128, bn0 = blockIdx.y * NB;
    const int wm = (wid >> 1) * 32, wn = (wid & 1) * (NB / 2);

    const int r0 = t >> 2, c4 = t & 3;
    const int cmask = (1 << logC) - 1;
    long ab[2]; const int* ib[2];
#pragma unroll
    for (int r = 0; r < 2; r++) {
        int m = bm0 + r0 + r * 64; if (m >= M) m = M - 1;
        int bI = m / VP, v = m - bI * VP;
        if (idx) { ab[r] = (long)bI * VP * lda; ib[r] = idx + v * LSP; }
        else     { ab[r] = (long)m * lda;       ib[r] = nullptr; }
    }

    const uint32_t la15 = lane & 15, lhi = lane >> 4, l7 = lane & 7, l8 = (lane >> 3) & 1;
    const int nkt = K >> 5;

    float acc[2][HALVES * 4][4];
#pragma unroll
    for (int i = 0; i < 2; i++)
#pragma unroll
        for (int j = 0; j < HALVES * 4; j++)
#pragma unroll
            for (int r = 0; r < 4; r++) acc[i][j][r] = 0.f;

    auto issue = [&](int kt, int p) {
        const int k0 = kt << 5;
        const uint32_t base = sbs + p * STG;
#pragma unroll
        for (int r = 0; r < 2; r++) {
            long off = idx ? (ab[r] + (long)ib[r][k0 >> logC] * lda + (k0 & cmask))
                           : (ab[r] + k0);
            cpa(base + (r0 + r * 64) * APITCH + c4 * 16, Ah + off + c4 * 8);
        }
#pragma unroll
        for (int i = t; i < BCH; i += 256) {
            const int pl  = i / (4 * NB);
            const int rem = i - pl * (4 * NB);
            const int row = rem / (NB / 8);
            const int col = rem - row * (NB / 8);
            const hf* Wp = pl ? Wl : Wh;
            cpa(base + ASTG + pl * BPL + row * BP + col * 16,
                Wp + (long)(k0 + row) * ldn + bn0 + col * 8);
        }
        CPCOMMIT();
    };

    issue(0, 0);
    issue(1, 1);

    for (int kt = 0; kt < nkt; kt++) {
        const int p = kt % 3;
        CPWAIT1();
        __syncthreads();
        const uint32_t base = sbs + p * STG;
#pragma unroll
        for (int ks = 0; ks < 2; ks++) {
            const uint32_t ao = base + (wm + la15) * APITCH + (ks * 16 + lhi * 8) * 2;
            uint32_t ah0[4], ah1[4];
            ldsm4(ao,               ah0);
            ldsm4(ao + 16 * APITCH, ah1);
            const uint32_t brow = (uint32_t)(ks * 16 + l7 + l8 * 8) * BP;
#pragma unroll
            for (int h = 0; h < HALVES; h++) {
                const uint32_t bo = base + ASTG + brow + (wn + h * 32 + lhi * 8) * 2;
                uint32_t bh[8], bl[8];
                ldsm4t(bo,            bh);
                ldsm4t(bo + 32,       bh + 4);
                ldsm4t(bo + BPL,      bl);
                ldsm4t(bo + BPL + 32, bl + 4);
                // pass 1: ah * bh  (8 independent accs)
#pragma unroll
                for (int nf = 0; nf < 4; nf++) mma_f16(acc[0][h * 4 + nf], ah0, bh + nf * 2);
#pragma unroll
                for (int nf = 0; nf < 4; nf++) mma_f16(acc[1][h * 4 + nf], ah1, bh + nf * 2);
                // pass 2: ah * bl
#pragma unroll
                for (int nf = 0; nf < 4; nf++) mma_f16(acc[0][h * 4 + nf], ah0, bl + nf * 2);
#pragma unroll
                for (int nf = 0; nf < 4; nf++) mma_f16(acc[1][h * 4 + nf], ah1, bl + nf * 2);
            }
        }
        if (kt + 2 < nkt) issue(kt + 2, (kt + 2) % 3);
        else CPCOMMIT();
    }

    // ---- epilogue
#pragma unroll
    for (int mf = 0; mf < 2; mf++) {
#pragma unroll
        for (int hh = 0; hh < 2; hh++) {
            const int m = bm0 + wm + mf * 16 + (lane >> 2) + hh * 8;
            if (m >= M) continue;
            const int bI = m / VP, v = m - bI * VP;
            const bool zd = (flags & F_ZDUM) && (v == V_);
            const long orow = (long)m * ldo;
            const long rrow = (long)m * ldr;
#pragma unroll
            for (int h = 0; h < HALVES; h++) {
#pragma unroll
                for (int nf = 0; nf < 4; nf++) {
                    const int n = bn0 + wn + h * 32 + nf * 8 + 2 * (lane & 3);
                    float f0 = acc[mf][h * 4 + nf][hh * 2 + 0];
                    float f1 = acc[mf][h * 4 + nf][hh * 2 + 1];
                    if (bias)   { f0 += bias[n];            f1 += bias[n + 1]; }
                    if (bias_b) { f0 += bias_b[bI * N + n]; f1 += bias_b[bI * N + n + 1]; }
                    if (Rh)     { f0 += pjoin(Rh, Rl, rrow + n); f1 += pjoin(Rh, Rl, rrow + n + 1); }
                    if (flags & F_RELU) { f0 = fmaxf(f0, 0.f); f1 = fmaxf(f1, 0.f); }
                    if (zd) { f0 = 0.f; f1 = 0.f; }
                    hf h0, l0, h1, l1;
                    fsplit2(f0, h0, l0); fsplit2(f1, h1, l1);
                    __half2 ph; ph.x = h0; ph.y = h1;
                    __half2 pl2; pl2.x = l0; pl2.y = l1;
                    *(__half2*)(Oh + orow + n) = ph;
                    *(__half2*)(Ol + orow + n) = pl2;
                }
            }
        }
    }
}

// ---------------- prep kernels ----------------
__global__ void xprep(const float* __restrict__ x, hf* __restrict__ Xh, hf* __restrict__ Xl)
{
    long i = (long)blockIdx.x * 256 + threadIdx.x;
    if (i >= (long)M_TOT * 512) return;
    int m = (int)(i >> 9), k = (int)(i & 511);
    int b = m / VP, v = m - b * VP;
    float val = 0.f;
    if (v < V_ && k < 479) val = x[((long)(b * V_ + v)) * 479 + k];
    fsplit2(val, Xh[i], Xl[i]);
}

#define NSEG 12
struct WSegs {
    const float* src[NSEG];
    hf* oh[NSEG]; hf* ol[NSEG];
    int N[NSEG]; int K[NSEG];
    long n[NSEG];
};
__global__ void wprep_all(WSegs s)
{
    const int seg = blockIdx.y;
    long i = (long)blockIdx.x * 256 + threadIdx.x;
    if (i >= s.n[seg]) return;
    const int N = s.N[seg];
    const int k = (int)(i / N);
    float v = (k < s.K[seg]) ? s.src[seg][i] : 0.f;
    fsplit2(v, s.oh[seg][i], s.ol[seg][i]);
}
__global__ void pad_k() {}

// ---------------- maxpool / gterm / final ----------------
__global__ void maxpool1(const hf* __restrict__ fh, const hf* __restrict__ fl)
{
    int chunk = blockIdx.x, b = blockIdx.y, n = threadIdx.x;
    int v0 = chunk * 128;
    float m = -FLT_MAX;
    for (int i = 0; i < 128; i++) {
        int v = v0 + i;
        if (v < V_) m = fmaxf(m, pjoin(fh, fl, (long)(b * VP + v) * 128 + n));
    }
    g_part[(b * NCHUNK + chunk) * 128 + n] = m;
}
__global__ void maxpool2()
{
    int b = blockIdx.x, n = threadIdx.x;
    float m = -FLT_MAX;
    for (int c = 0; c < NCHUNK; c++) m = fmaxf(m, g_part[(b * NCHUNK + c) * 128 + n]);
    g_gfs[b * 128 + n] = m;
}
__global__ void gterm_k(const float* __restrict__ Wo1)
{
    int b = blockIdx.x, n = threadIdx.x;
    float s = 0.f;
    for (int c = 0; c < 128; c++)
        s = fmaf(g_gfs[b * 128 + c], Wo1[(384 + c) * 256 + n], s);
    g_gterm[b * 256 + n] = s;
}
__global__ void out_k(const hf* __restrict__ h2h, const hf* __restrict__ h2l,
                      const float* __restrict__ Wo3, const float* __restrict__ bo3,
                      float* __restrict__ out)
{
    __shared__ float w[384];
    int t = threadIdx.x;
    if (t < 128) { w[t] = Wo3[t]; w[t + 128] = Wo3[t + 128]; w[t + 256] = Wo3[t + 256]; }
    __syncthreads();
    int warp = t >> 5, lane = t & 31;
    int u = blockIdx.x * 4 + warp;
    if (u >= BB * V_) return;
    int b = u / V_, v = u - b * V_;
    long row = (long)(b * VP + v) * 128;
    float s0 = 0.f, s1 = 0.f, s2 = 0.f;
    for (int c = lane; c < 128; c += 32) {
        float h = pjoin(h2h, h2l, row + c);
        s0 = fmaf(h, w[c * 3 + 0], s0);
        s1 = fmaf(h, w[c * 3 + 1], s1);
        s2 = fmaf(h, w[c * 3 + 2], s2);
    }
    for (int o = 16; o > 0; o >>= 1) {
        s0 += __shfl_down_sync(0xffffffffu, s0, o);
        s1 += __shfl_down_sync(0xffffffffu, s1, o);
        s2 += __shfl_down_sync(0xffffffffu, s2, o);
    }
    if (lane == 0) {
        out[u * 3 + 0] = s0 + bo3[0];
        out[u * 3 + 1] = s1 + bo3[1];
        out[u * 3 + 2] = s2 + bo3[2];
    }
}

// ---------------- host orchestration ----------------
static void* sym(const void* s) { void* p; cudaGetSymbolAddress(&p, s); return p; }

#define SMEM128 (3*(ASTG + 2*32*(128*2+16)))   // 82944
#define SMEM64  (3*(ASTG + 2*32*(64*2+16)))    // 58368

static void G128(const hf* Ah, const hf* Wh, const hf* Wl,
                 hf* Oh, hf* Ol, const int* idx, const float* bias, const float* bb,
                 const hf* Rh, const hf* Rl,
                 int N, int K, int lda, int ldn, int ldo, int ldr, int logC, int flags)
{
    dim3 grid((M_TOT + 127) / 128, N / 128);
    gemm_tc<128><<<grid, 256, SMEM128>>>(Ah, Wh, Wl, Oh, Ol, idx, bias, bb, Rh, Rl,
                                         M_TOT, N, K, lda, ldn, ldo, ldr, logC, flags);
}
static void G64(const hf* Ah, const hf* Wh, const hf* Wl,
                hf* Oh, hf* Ol, const int* idx, const float* bias, const float* bb,
                const hf* Rh, const hf* Rl,
                int N, int K, int lda, int ldn, int ldo, int ldr, int logC, int flags)
{
    dim3 grid((M_TOT + 127) / 128, N / 64);
    gemm_tc<64><<<grid, 256, SMEM64>>>(Ah, Wh, Wl, Oh, Ol, idx, bias, bb, Rh, Rl,
                                       M_TOT, N, K, lda, ldn, ldo, ldr, logC, flags);
}

extern "C" void kernel_launch(void* const* d_in, const int* in_sizes, int n_in,
                              void* d_out, int out_size)
{
    (void)in_sizes; (void)n_in; (void)out_size;
    const float* x       = (const float*)d_in[0];
    const int*   sidx    = (const int*)  d_in[1];
    const float* W_point = (const float*)d_in[2];
    const float* res1_W  = (const float*)d_in[3];
    const float* res1_b  = (const float*)d_in[4];
    const float* W_mid   = (const float*)d_in[5];
    const float* ress_W  = (const float*)d_in[6];
    const float* ress_b  = (const float*)d_in[7];
    const float* Wo1     = (const float*)d_in[8];
    const float* bo1     = (const float*)d_in[9];
    const float* Wo2     = (const float*)d_in[10];
    const float* bo2     = (const float*)d_in[11];
    const float* Wo3     = (const float*)d_in[12];
    const float* bo3     = (const float*)d_in[13];
    float* out = (float*)d_out;

    cudaFuncSetAttribute(gemm_tc<128>, cudaFuncAttributeMaxDynamicSharedMemorySize, SMEM128);
    cudaFuncSetAttribute(gemm_tc<64>,  cudaFuncAttributeMaxDynamicSharedMemorySize, SMEM64);

    hf *Xh = (hf*)sym(g_Xh), *Xl = (hf*)sym(g_Xl);
    hf *Hbh = (hf*)sym(g_Hbh), *Hbl = (hf*)sym(g_Hbl);
    hf *T1h = (hf*)sym(g_T1h), *T1l = (hf*)sym(g_T1l);
    hf *T2h = (hf*)sym(g_T2h), *T2l = (hf*)sym(g_T2l);
    hf *F1h = (hf*)sym(g_F1h), *F1l = (hf*)sym(g_F1l);
    hf *F2h = (hf*)sym(g_F2h), *F2l = (hf*)sym(g_F2l);
    hf *H2h = (hf*)sym(g_H2h), *H2l = (hf*)sym(g_H2l);
    hf *Wpth = (hf*)sym(g_Wpth), *Wptl = (hf*)sym(g_Wptl);
    hf *R1ah = (hf*)sym(g_R1ah), *R1al = (hf*)sym(g_R1al);
    hf *R1bh = (hf*)sym(g_R1bh), *R1bl = (hf*)sym(g_R1bl);
    hf *Wmh  = (hf*)sym(g_Wmh),  *Wml  = (hf*)sym(g_Wml);
    hf *RSh  = (hf*)sym(g_RSh),  *RSl  = (hf*)sym(g_RSl);
    hf *Wo1h = (hf*)sym(g_Wo1h), *Wo1l = (hf*)sym(g_Wo1l);
    hf *Wo2h = (hf*)sym(g_Wo2h), *Wo2l = (hf*)sym(g_Wo2l);
    float* gterm = (float*)sym(g_gterm);

    // ---- prep (2 launches)
    xprep<<<(unsigned)(((long)M_TOT * 512 + 255) / 256), 256>>>(x, Xh, Xl);
    {
        WSegs s;
        int si = 0;
        auto add = [&](const float* src, hf* oh, hf* ol, int K, int N, int Kpad) {
            s.src[si] = src; s.oh[si] = oh; s.ol[si] = ol;
            s.N[si] = N; s.K[si] = K; s.n[si] = (long)Kpad * N; si++;
        };
        add(W_point, Wpth, Wptl, 479, 256, 512);
        add(res1_W,              R1ah, R1al, 4096, 256, 4096);
        add(res1_W + 4096 * 256, R1bh, R1bl, 4096, 256, 4096);
        add(W_mid, Wmh, Wml, 256, 128, 256);
        for (int j = 0; j < 6; j++)
            add(ress_W + (long)j * 2048 * 128, RSh + (long)j * 2048 * 128,
                RSl + (long)j * 2048 * 128, 2048, 128, 2048);
        add(Wo1, Wo1h, Wo1l, 384, 256, 384);
        add(Wo2, Wo2h, Wo2l, 256, 128, 256);
        wprep_all<<<dim3(4096, NSEG), 256>>>(s);
    }

    // 1) pfs = relu(x @ W_point) -> Hb cols 0:256      (launch idx 2)
    G128(Xh, Wpth, Wptl, Hbh, Hbl, nullptr, nullptr, nullptr, nullptr, nullptr,
         256, 512, 512, 256, 384, 0, 0, F_RELU | F_ZDUM);
    // pads so ncu (-s 5) captures the big res1 GEMM next round (idx 3,4)
    pad_k<<<1, 32>>>();
    pad_k<<<1, 32>>>();
    // 2) res1 conv1                                     (launch idx 5)
    G128(Hbh, R1ah, R1al, T1h, T1l, sidx, res1_b, nullptr, nullptr, nullptr,
         256, 4096, 384, 256, 256, 0, 8, F_RELU | F_ZDUM);
    // 3) res1 conv2 + residual(pfs)
    G128(T1h, R1bh, R1bl, T2h, T2l, sidx, res1_b + 256, nullptr, Hbh, Hbl,
         256, 4096, 256, 256, 256, 384, 8, F_RELU | F_ZDUM);
    // 4) fs = (r1 @ W_mid) * zp
    G128(T2h, Wmh, Wml, F1h, F1l, nullptr, nullptr, nullptr, nullptr, nullptr,
         128, 256, 256, 128, 128, 0, 0, F_ZDUM);
    // 5) masked global max-pool
    maxpool1<<<dim3(NCHUNK, BB), 128>>>(F1h, F1l);
    maxpool2<<<BB, 128>>>();
    // 6) three residual blocks (C=128); block 3 conv2 writes Hb cols 256:384
    for (int i = 0; i < 3; i++) {
        const hf* W0h = RSh + (long)(i * 2 + 0) * 2048 * 128;
        const hf* W0l = RSl + (long)(i * 2 + 0) * 2048 * 128;
        const hf* W1h = RSh + (long)(i * 2 + 1) * 2048 * 128;
        const hf* W1l = RSl + (long)(i * 2 + 1) * 2048 * 128;
        const float* b0 = ress_b + (i * 2 + 0) * 128;
        const float* b1 = ress_b + (i * 2 + 1) * 128;
        G64(F1h, W0h, W0l, F2h, F2l, sidx, b0, nullptr, nullptr, nullptr,
            128, 2048, 128, 128, 128, 0, 7, F_RELU | F_ZDUM);
        if (i < 2)
            G64(F2h, W1h, W1l, F1h, F1l, sidx, b1, nullptr, F1h, F1l,
                128, 2048, 128, 128, 128, 128, 7, F_RELU | F_ZDUM);
        else
            G64(F2h, W1h, W1l, Hbh + 256, Hbl + 256, sidx, b1, nullptr, F1h, F1l,
                128, 2048, 128, 128, 384, 128, 7, F_RELU | F_ZDUM);
    }
    // 7) gterm[b] = gfs[b] @ Wo1[384:512]
    gterm_k<<<BB, 256>>>(Wo1);
    // 8) h1 = relu([pfs|fs] @ Wo1[0:384] + bo1 + gterm)
    G128(Hbh, Wo1h, Wo1l, T1h, T1l, nullptr, bo1, gterm, nullptr, nullptr,
         256, 384, 384, 256, 256, 0, 0, F_RELU);
    // 9) h2 = relu(h1 @ Wo2 + bo2)
    G128(T1h, Wo2h, Wo2l, H2h, H2l, nullptr, bo2, nullptr, nullptr, nullptr,
         128, 256, 256, 128, 128, 0, 0, F_RELU);
    // 10) out = h2 @ Wo3 + bo3
    out_k<<<(BB * V_ + 3) / 4, 128>>>(H2h, H2l, Wo3, bo3, out);
}

// round 8
// speedup vs baseline: 3.9296x; 1.0236x over previous
#include <cuda_runtime.h>
#include <cuda_fp16.h>
#include <float.h>
#include <stdint.h>

// ---------------- problem constants ----------------
#define BB   2
#define V_   12000
#define VP   12001
#define LSP  16
#define M_TOT (BB*VP)          // 24002
#define NCHUNK 94

typedef __half hf;

// ---------------- scratch (device globals) ----------------
// hi planes feed GEMM A; lo planes only where read (residual / pool / final)
__device__ hf g_Xh [M_TOT*512];
__device__ hf g_Hbh[M_TOT*384], g_Hbl[M_TOT*384];   // [pfs(256) | fs3(128)]
__device__ hf g_T1h[M_TOT*256];
__device__ hf g_T2h[M_TOT*256];
__device__ hf g_F1h[M_TOT*128], g_F1l[M_TOT*128];
__device__ hf g_F2h[M_TOT*128];
__device__ hf g_H2h[M_TOT*128], g_H2l[M_TOT*128];
// weights split to fp16 hi/lo planes, layout [K][N]
__device__ hf g_Wpth[512*256],   g_Wptl[512*256];
__device__ hf g_R1ah[4096*256],  g_R1al[4096*256];
__device__ hf g_R1bh[4096*256],  g_R1bl[4096*256];
__device__ hf g_Wmh [256*128],   g_Wml [256*128];
__device__ hf g_RSh [6*2048*128],g_RSl [6*2048*128];
__device__ hf g_Wo1h[384*256],   g_Wo1l[384*256];
__device__ hf g_Wo2h[256*128],   g_Wo2l[256*128];
__device__ float g_part [BB*NCHUNK*128];
__device__ float g_gfs  [BB*128];
__device__ float g_gterm[BB*256];

enum { F_RELU = 1, F_ZDUM = 2, F_WLO = 4 };

// ---------------- helpers ----------------
__device__ __forceinline__ uint32_t s2u(const void* p) {
    uint32_t a;
    asm("{ .reg .u64 t; cvta.to.shared.u64 t, %1; cvt.u32.u64 %0, t; }" : "=r"(a) : "l"(p));
    return a;
}
__device__ __forceinline__ void ldsm4(uint32_t addr, uint32_t* r) {
    asm volatile("ldmatrix.sync.aligned.m8n8.x4.shared.b16 {%0,%1,%2,%3}, [%4];"
        : "=r"(r[0]), "=r"(r[1]), "=r"(r[2]), "=r"(r[3]) : "r"(addr));
}
__device__ __forceinline__ void ldsm4t(uint32_t addr, uint32_t* r) {
    asm volatile("ldmatrix.sync.aligned.m8n8.x4.trans.shared.b16 {%0,%1,%2,%3}, [%4];"
        : "=r"(r[0]), "=r"(r[1]), "=r"(r[2]), "=r"(r[3]) : "r"(addr));
}
__device__ __forceinline__ void mma_f16(float* c, const uint32_t* a, const uint32_t* b) {
    asm volatile("mma.sync.aligned.m16n8k16.row.col.f32.f16.f16.f32 "
        "{%0,%1,%2,%3}, {%4,%5,%6,%7}, {%8,%9}, {%0,%1,%2,%3};"
        : "+f"(c[0]), "+f"(c[1]), "+f"(c[2]), "+f"(c[3])
        : "r"(a[0]), "r"(a[1]), "r"(a[2]), "r"(a[3]), "r"(b[0]), "r"(b[1]));
}
__device__ __forceinline__ void cpa(uint32_t dst, const void* src) {
    asm volatile("cp.async.ca.shared.global [%0], [%1], 16;" :: "r"(dst), "l"(src) : "memory");
}
#define CPCOMMIT() asm volatile("cp.async.commit_group;" ::: "memory")
#define CPWAIT1()  asm volatile("cp.async.wait_group 1;" ::: "memory")

__device__ __forceinline__ void fsplit2(float f, hf& h, hf& l) {
    h = __float2half_rn(f);
    l = __float2half_rn(f - __half2float(h));
}
__device__ __forceinline__ float pjoin(const hf* H, const hf* L, long i) {
    return __half2float(H[i]) + __half2float(L[i]);
}

// ---------------- smem geometry ----------------
#define APITCH 80
#define ASTG   (128*APITCH)              // 10240 (single A plane)

// ---------------- mma.sync fp16x2 fused (gather-)GEMM, 3-stage cp.async ----------------
// NB: block N tile; MW: m16-fragments per warp. 8 warps, warp tile (MW*16) x 32.
template<int NB, int MW>
__global__ __launch_bounds__(256, 2)
void gemm_tc(const hf* __restrict__ Ah,
             const hf* __restrict__ Wh, const hf* __restrict__ Wl,
             hf* __restrict__ Oh, hf* __restrict__ Ol,
             const int* __restrict__ idx,
             const float* __restrict__ bias, const float* __restrict__ bias_b,
             const hf* __restrict__ Rh, const hf* __restrict__ Rl,
             int M, int N, int K, int lda, int ldn, int ldo, int ldr,
             int logC, int flags)
{
    constexpr int BP      = NB * 2 + 16;
    constexpr int BPL     = 32 * BP;
    constexpr int STG     = ASTG + 2 * BPL;
    constexpr int BCH     = 8 * NB;
    constexpr int WARPS_M = 128 / (MW * 16);
    static_assert(WARPS_M * (NB / 32) == 8, "8 warps");

    extern __shared__ char smem[];
    const uint32_t sbs = s2u(smem);
    const int t = threadIdx.x, wid = t >> 5, lane = t & 31;
    const int bm0 = blockIdx.x * 128, bn0 = blockIdx.y * NB;
    const int wm = (wid % WARPS_M) * (MW * 16), wn = (wid / WARPS_M) * 32;

    const int r0 = t >> 2, c4 = t & 3;
    const int cmask = (1 << logC) - 1;
    long ab[2]; const int* ib[2];
#pragma unroll
    for (int r = 0; r < 2; r++) {
        int m = bm0 + r0 + r * 64; if (m >= M) m = M - 1;
        int bI = m / VP, v = m - bI * VP;
        if (idx) { ab[r] = (long)bI * VP * lda; ib[r] = idx + v * LSP; }
        else     { ab[r] = (long)m * lda;       ib[r] = nullptr; }
    }

    const uint32_t la15 = lane & 15, lhi = lane >> 4, l7 = lane & 7, l8 = (lane >> 3) & 1;
    const int nkt = K >> 5;

    float acc[MW][4][4];
#pragma unroll
    for (int i = 0; i < MW; i++)
#pragma unroll
        for (int j = 0; j < 4; j++)
#pragma unroll
            for (int r = 0; r < 4; r++) acc[i][j][r] = 0.f;

    auto issue = [&](int kt, int p) {
        const int k0 = kt << 5;
        const uint32_t base = sbs + p * STG;
#pragma unroll
        for (int r = 0; r < 2; r++) {
            long off = idx ? (ab[r] + (long)ib[r][k0 >> logC] * lda + (k0 & cmask))
                           : (ab[r] + k0);
            cpa(base + (r0 + r * 64) * APITCH + c4 * 16, Ah + off + c4 * 8);
        }
#pragma unroll
        for (int i = t; i < BCH; i += 256) {
            const int pl  = i / (4 * NB);
            const int rem = i - pl * (4 * NB);
            const int row = rem / (NB / 8);
            const int col = rem - row * (NB / 8);
            const hf* Wp = pl ? Wl : Wh;
            cpa(base + ASTG + pl * BPL + row * BP + col * 16,
                Wp + (long)(k0 + row) * ldn + bn0 + col * 8);
        }
        CPCOMMIT();
    };

    issue(0, 0);
    issue(1, 1);

    for (int kt = 0; kt < nkt; kt++) {
        const int p = kt % 3;
        CPWAIT1();
        __syncthreads();
        const uint32_t base = sbs + p * STG;
#pragma unroll
        for (int ks = 0; ks < 2; ks++) {
            uint32_t a[MW][4];
#pragma unroll
            for (int i = 0; i < MW; i++)
                ldsm4(base + (wm + i * 16 + la15) * APITCH + (ks * 16 + lhi * 8) * 2, a[i]);
            const uint32_t bo = base + ASTG + (uint32_t)(ks * 16 + l7 + l8 * 8) * BP
                               + (wn + lhi * 8) * 2;
            uint32_t bh[8], bl[8];
            ldsm4t(bo,            bh);
            ldsm4t(bo + 32,       bh + 4);
            ldsm4t(bo + BPL,      bl);
            ldsm4t(bo + BPL + 32, bl + 4);
            // pass 1: a * bh   (MW*4 independent accumulators)
#pragma unroll
            for (int i = 0; i < MW; i++)
#pragma unroll
                for (int nf = 0; nf < 4; nf++) mma_f16(acc[i][nf], a[i], bh + nf * 2);
            // pass 2: a * bl
#pragma unroll
            for (int i = 0; i < MW; i++)
#pragma unroll
                for (int nf = 0; nf < 4; nf++) mma_f16(acc[i][nf], a[i], bl + nf * 2);
        }
        if (kt + 2 < nkt) issue(kt + 2, (kt + 2) % 3);
        else CPCOMMIT();
    }

    // ---- epilogue
    const bool wlo = (flags & F_WLO) != 0;
#pragma unroll
    for (int i = 0; i < MW; i++) {
#pragma unroll
        for (int hh = 0; hh < 2; hh++) {
            const int m = bm0 + wm + i * 16 + (lane >> 2) + hh * 8;
            if (m >= M) continue;
            const int bI = m / VP, v = m - bI * VP;
            const bool zd = (flags & F_ZDUM) && (v == V_);
            const long orow = (long)m * ldo;
            const long rrow = (long)m * ldr;
#pragma unroll
            for (int nf = 0; nf < 4; nf++) {
                const int n = bn0 + wn + nf * 8 + 2 * (lane & 3);
                float f0 = acc[i][nf][hh * 2 + 0];
                float f1 = acc[i][nf][hh * 2 + 1];
                if (bias)   { f0 += bias[n];            f1 += bias[n + 1]; }
                if (bias_b) { f0 += bias_b[bI * N + n]; f1 += bias_b[bI * N + n + 1]; }
                if (Rh)     { f0 += pjoin(Rh, Rl, rrow + n); f1 += pjoin(Rh, Rl, rrow + n + 1); }
                if (flags & F_RELU) { f0 = fmaxf(f0, 0.f); f1 = fmaxf(f1, 0.f); }
                if (zd) { f0 = 0.f; f1 = 0.f; }
                hf h0, l0, h1, l1;
                fsplit2(f0, h0, l0); fsplit2(f1, h1, l1);
                __half2 ph; ph.x = h0; ph.y = h1;
                *(__half2*)(Oh + orow + n) = ph;
                if (wlo) {
                    __half2 pl2; pl2.x = l0; pl2.y = l1;
                    *(__half2*)(Ol + orow + n) = pl2;
                }
            }
        }
    }
}

// ---------------- prep kernels ----------------
__global__ void xprep(const float* __restrict__ x, hf* __restrict__ Xh)
{
    long i = (long)blockIdx.x * 256 + threadIdx.x;
    if (i >= (long)M_TOT * 512) return;
    int m = (int)(i >> 9), k = (int)(i & 511);
    int b = m / VP, v = m - b * VP;
    float val = 0.f;
    if (v < V_ && k < 479) val = x[((long)(b * V_ + v)) * 479 + k];
    Xh[i] = __float2half_rn(val);
}

#define NSEG 12
struct WSegs {
    const float* src[NSEG];
    hf* oh[NSEG]; hf* ol[NSEG];
    int N[NSEG]; int K[NSEG];
    long n[NSEG];
};
__global__ void wprep_all(WSegs s)
{
    const int seg = blockIdx.y;
    long i = (long)blockIdx.x * 256 + threadIdx.x;
    if (i >= s.n[seg]) return;
    const int N = s.N[seg];
    const int k = (int)(i / N);
    float v = (k < s.K[seg]) ? s.src[seg][i] : 0.f;
    fsplit2(v, s.oh[seg][i], s.ol[seg][i]);
}

// ---------------- maxpool / gterm / final ----------------
__global__ void maxpool1(const hf* __restrict__ fh, const hf* __restrict__ fl)
{
    int chunk = blockIdx.x, b = blockIdx.y, n = threadIdx.x;
    int v0 = chunk * 128;
    float m = -FLT_MAX;
    for (int i = 0; i < 128; i++) {
        int v = v0 + i;
        if (v < V_) m = fmaxf(m, pjoin(fh, fl, (long)(b * VP + v) * 128 + n));
    }
    g_part[(b * NCHUNK + chunk) * 128 + n] = m;
}
__global__ void maxpool2()
{
    int b = blockIdx.x, n = threadIdx.x;
    float m = -FLT_MAX;
    for (int c = 0; c < NCHUNK; c++) m = fmaxf(m, g_part[(b * NCHUNK + c) * 128 + n]);
    g_gfs[b * 128 + n] = m;
}
__global__ void gterm_k(const float* __restrict__ Wo1)
{
    int b = blockIdx.x, n = threadIdx.x;
    float s = 0.f;
    for (int c = 0; c < 128; c++)
        s = fmaf(g_gfs[b * 128 + c], Wo1[(384 + c) * 256 + n], s);
    g_gterm[b * 256 + n] = s;
}
__global__ void out_k(const hf* __restrict__ h2h, const hf* __restrict__ h2l,
                      const float* __restrict__ Wo3, const float* __restrict__ bo3,
                      float* __restrict__ out)
{
    __shared__ float w[384];
    int t = threadIdx.x;
    if (t < 128) { w[t] = Wo3[t]; w[t + 128] = Wo3[t + 128]; w[t + 256] = Wo3[t + 256]; }
    __syncthreads();
    int warp = t >> 5, lane = t & 31;
    int u = blockIdx.x * 4 + warp;
    if (u >= BB * V_) return;
    int b = u / V_, v = u - b * V_;
    long row = (long)(b * VP + v) * 128;
    float s0 = 0.f, s1 = 0.f, s2 = 0.f;
    for (int c = lane; c < 128; c += 32) {
        float h = pjoin(h2h, h2l, row + c);
        s0 = fmaf(h, w[c * 3 + 0], s0);
        s1 = fmaf(h, w[c * 3 + 1], s1);
        s2 = fmaf(h, w[c * 3 + 2], s2);
    }
    for (int o = 16; o > 0; o >>= 1) {
        s0 += __shfl_down_sync(0xffffffffu, s0, o);
        s1 += __shfl_down_sync(0xffffffffu, s1, o);
        s2 += __shfl_down_sync(0xffffffffu, s2, o);
    }
    if (lane == 0) {
        out[u * 3 + 0] = s0 + bo3[0];
        out[u * 3 + 1] = s1 + bo3[1];
        out[u * 3 + 2] = s2 + bo3[2];
    }
}

// ---------------- host orchestration ----------------
static void* sym(const void* s) { void* p; cudaGetSymbolAddress(&p, s); return p; }

#define SMEM128 (3*(ASTG + 2*32*(128*2+16)))   // 82944
#define SMEM64  (3*(ASTG + 2*32*(64*2+16)))    // 58368

static void G128(const hf* Ah, const hf* Wh, const hf* Wl,
                 hf* Oh, hf* Ol, const int* idx, const float* bias, const float* bb,
                 const hf* Rh, const hf* Rl,
                 int N, int K, int lda, int ldn, int ldo, int ldr, int logC, int flags)
{
    dim3 grid((M_TOT + 127) / 128, N / 128);
    gemm_tc<128, 4><<<grid, 256, SMEM128>>>(Ah, Wh, Wl, Oh, Ol, idx, bias, bb, Rh, Rl,
                                            M_TOT, N, K, lda, ldn, ldo, ldr, logC, flags);
}
static void G64(const hf* Ah, const hf* Wh, const hf* Wl,
                hf* Oh, hf* Ol, const int* idx, const float* bias, const float* bb,
                const hf* Rh, const hf* Rl,
                int N, int K, int lda, int ldn, int ldo, int ldr, int logC, int flags)
{
    dim3 grid((M_TOT + 127) / 128, N / 64);
    gemm_tc<64, 2><<<grid, 256, SMEM64>>>(Ah, Wh, Wl, Oh, Ol, idx, bias, bb, Rh, Rl,
                                          M_TOT, N, K, lda, ldn, ldo, ldr, logC, flags);
}

extern "C" void kernel_launch(void* const* d_in, const int* in_sizes, int n_in,
                              void* d_out, int out_size)
{
    (void)in_sizes; (void)n_in; (void)out_size;
    const float* x       = (const float*)d_in[0];
    const int*   sidx    = (const int*)  d_in[1];
    const float* W_point = (const float*)d_in[2];
    const float* res1_W  = (const float*)d_in[3];
    const float* res1_b  = (const float*)d_in[4];
    const float* W_mid   = (const float*)d_in[5];
    const float* ress_W  = (const float*)d_in[6];
    const float* ress_b  = (const float*)d_in[7];
    const float* Wo1     = (const float*)d_in[8];
    const float* bo1     = (const float*)d_in[9];
    const float* Wo2     = (const float*)d_in[10];
    const float* bo2     = (const float*)d_in[11];
    const float* Wo3     = (const float*)d_in[12];
    const float* bo3     = (const float*)d_in[13];
    float* out = (float*)d_out;

    cudaFuncSetAttribute((const void*)gemm_tc<128, 4>,
                         cudaFuncAttributeMaxDynamicSharedMemorySize, SMEM128);
    cudaFuncSetAttribute((const void*)gemm_tc<64, 2>,
                         cudaFuncAttributeMaxDynamicSharedMemorySize, SMEM64);

    hf *Xh = (hf*)sym(g_Xh);
    hf *Hbh = (hf*)sym(g_Hbh), *Hbl = (hf*)sym(g_Hbl);
    hf *T1h = (hf*)sym(g_T1h);
    hf *T2h = (hf*)sym(g_T2h);
    hf *F1h = (hf*)sym(g_F1h), *F1l = (hf*)sym(g_F1l);
    hf *F2h = (hf*)sym(g_F2h);
    hf *H2h = (hf*)sym(g_H2h), *H2l = (hf*)sym(g_H2l);
    hf *Wpth = (hf*)sym(g_Wpth), *Wptl = (hf*)sym(g_Wptl);
    hf *R1ah = (hf*)sym(g_R1ah), *R1al = (hf*)sym(g_R1al);
    hf *R1bh = (hf*)sym(g_R1bh), *R1bl = (hf*)sym(g_R1bl);
    hf *Wmh  = (hf*)sym(g_Wmh),  *Wml  = (hf*)sym(g_Wml);
    hf *RSh  = (hf*)sym(g_RSh),  *RSl  = (hf*)sym(g_RSl);
    hf *Wo1h = (hf*)sym(g_Wo1h), *Wo1l = (hf*)sym(g_Wo1l);
    hf *Wo2h = (hf*)sym(g_Wo2h), *Wo2l = (hf*)sym(g_Wo2l);
    float* gterm = (float*)sym(g_gterm);

    // ---- prep (launch 0, 1)
    xprep<<<(unsigned)(((long)M_TOT * 512 + 255) / 256), 256>>>(x, Xh);
    {
        WSegs s;
        int si = 0;
        auto add = [&](const float* src, hf* oh, hf* ol, int K, int N, int Kpad) {
            s.src[si] = src; s.oh[si] = oh; s.ol[si] = ol;
            s.N[si] = N; s.K[si] = K; s.n[si] = (long)Kpad * N; si++;
        };
        add(W_point, Wpth, Wptl, 479, 256, 512);
        add(res1_W,              R1ah, R1al, 4096, 256, 4096);
        add(res1_W + 4096 * 256, R1bh, R1bl, 4096, 256, 4096);
        add(W_mid, Wmh, Wml, 256, 128, 256);
        for (int j = 0; j < 6; j++)
            add(ress_W + (long)j * 2048 * 128, RSh + (long)j * 2048 * 128,
                RSl + (long)j * 2048 * 128, 2048, 128, 2048);
        add(Wo1, Wo1h, Wo1l, 384, 256, 384);
        add(Wo2, Wo2h, Wo2l, 256, 128, 256);
        wprep_all<<<dim3(4096, NSEG), 256>>>(s);
    }

    // 1) pfs = relu(x @ W_point) -> Hb cols 0:256    (launch 2)
    G128(Xh, Wpth, Wptl, Hbh, Hbl, nullptr, nullptr, nullptr, nullptr, nullptr,
         256, 512, 512, 256, 384, 0, 0, F_RELU | F_ZDUM | F_WLO);
    // 2) res1 conv1 (K=4096)                          (launch 3 -> ncu target)
    G128(Hbh, R1ah, R1al, T1h, nullptr, sidx, res1_b, nullptr, nullptr, nullptr,
         256, 4096, 384, 256, 256, 0, 8, F_RELU | F_ZDUM);
    // 3) res1 conv2 + residual(pfs)
    G128(T1h, R1bh, R1bl, T2h, nullptr, sidx, res1_b + 256, nullptr, Hbh, Hbl,
         256, 4096, 256, 256, 256, 384, 8, F_RELU | F_ZDUM);
    // 4) fs = (r1 @ W_mid) * zp
    G128(T2h, Wmh, Wml, F1h, F1l, nullptr, nullptr, nullptr, nullptr, nullptr,
         128, 256, 256, 128, 128, 0, 0, F_ZDUM | F_WLO);
    // 5) masked global max-pool
    maxpool1<<<dim3(NCHUNK, BB), 128>>>(F1h, F1l);
    maxpool2<<<BB, 128>>>();
    // 6) three residual blocks (C=128); block 3 conv2 writes Hb cols 256:384
    for (int i = 0; i < 3; i++) {
        const hf* W0h = RSh + (long)(i * 2 + 0) * 2048 * 128;
        const hf* W0l = RSl + (long)(i * 2 + 0) * 2048 * 128;
        const hf* W1h = RSh + (long)(i * 2 + 1) * 2048 * 128;
        const hf* W1l = RSl + (long)(i * 2 + 1) * 2048 * 128;
        const float* b0 = ress_b + (i * 2 + 0) * 128;
        const float* b1 = ress_b + (i * 2 + 1) * 128;
        G64(F1h, W0h, W0l, F2h, nullptr, sidx, b0, nullptr, nullptr, nullptr,
            128, 2048, 128, 128, 128, 0, 7, F_RELU | F_ZDUM);
        if (i < 2)
            G64(F2h, W1h, W1l, F1h, F1l, sidx, b1, nullptr, F1h, F1l,
                128, 2048, 128, 128, 128, 128, 7, F_RELU | F_ZDUM | F_WLO);
        else
            G64(F2h, W1h, W1l, Hbh + 256, nullptr, sidx, b1, nullptr, F1h, F1l,
                128, 2048, 128, 128, 384, 128, 7, F_RELU | F_ZDUM);
    }
    // 7) gterm[b] = gfs[b] @ Wo1[384:512]
    gterm_k<<<BB, 256>>>(Wo1);
    // 8) h1 = relu([pfs|fs] @ Wo1[0:384] + bo1 + gterm)
    G128(Hbh, Wo1h, Wo1l, T1h, nullptr, nullptr, bo1, gterm, nullptr, nullptr,
         256, 384, 384, 256, 256, 0, 0, F_RELU);
    // 9) h2 = relu(h1 @ Wo2 + bo2)
    G128(T1h, Wo2h, Wo2l, H2h, H2l, nullptr, bo2, nullptr, nullptr, nullptr,
         128, 256, 256, 128, 128, 0, 0, F_RELU | F_WLO);
    // 10) out = h2 @ Wo3 + bo3
    out_k<<<(BB * V_ + 3) / 4, 128>>>(H2h, H2l, Wo3, bo3, out);
}